// round 11
// baseline (speedup 1.0000x reference)
#include <cuda_runtime.h>
#include <cuda_fp16.h>
#include <math.h>
#include <stdint.h>

#define D_MODEL 2048
#define NH 32
#define NKV 8
#define HD 64
#define BATCH 2
#define SEQ 2048
#define TOK (BATCH * SEQ)   // 4096
#define KVD (NKV * HD)      // 512
#define NQKV (D_MODEL + 2 * KVD)   // 3072: q | k | v columns

// ---------------- scratch (device globals; no allocation allowed) ----------
__device__ float  g_qkv[(size_t)TOK * NQKV];       // fused projection output
__device__ __half g_xh[(size_t)TOK * D_MODEL];
__device__ __half g_xl[(size_t)TOK * D_MODEL];
__device__ __half g_wh[(size_t)NQKV * D_MODEL];    // concat Wq^T|Wk^T|Wv^T hi
__device__ __half g_wl[(size_t)NQKV * D_MODEL];    // lo
__device__ __half g_woth[(size_t)D_MODEL * D_MODEL];
__device__ __half g_wotl[(size_t)D_MODEL * D_MODEL];
__device__ __half g_qh[(size_t)TOK * NH * HD];
__device__ __half g_ql[(size_t)TOK * NH * HD];
__device__ __half g_kh[(size_t)TOK * NKV * HD];
__device__ __half g_kl[(size_t)TOK * NKV * HD];
__device__ __half g_vth[(size_t)BATCH * NKV * HD * SEQ];
__device__ __half g_vtl[(size_t)BATCH * NKV * HD * SEQ];
__device__ __half g_oh[(size_t)TOK * NH * HD];
__device__ __half g_ol[(size_t)TOK * NH * HD];

// ======================= helpers (portable PTX only) ========================
__device__ __forceinline__ uint32_t smem_u32(const void* p) {
    uint32_t a;
    asm("{ .reg .u64 t; cvta.to.shared.u64 t, %1; cvt.u32.u64 %0, t; }"
        : "=r"(a) : "l"(p));
    return a;
}
#define SWZ(o)   ((o) ^ (((o) >> 3) & 0x70))
#define SWZ64(o) ((o) ^ (((o) >> 3) & 0x30))

#define LDSM4(r, a) \
    asm volatile("ldmatrix.sync.aligned.m8n8.x4.shared.b16 {%0,%1,%2,%3}, [%4];" \
        : "=r"((r)[0]), "=r"((r)[1]), "=r"((r)[2]), "=r"((r)[3]) : "r"(a))

#define MMA_F16(c, a, b0, b1) \
    asm volatile("mma.sync.aligned.m16n8k16.row.col.f32.f16.f16.f32 " \
        "{%0,%1,%2,%3}, {%4,%5,%6,%7}, {%8,%9}, {%0,%1,%2,%3};" \
        : "+f"((c)[0]), "+f"((c)[1]), "+f"((c)[2]), "+f"((c)[3]) \
        : "r"((a)[0]), "r"((a)[1]), "r"((a)[2]), "r"((a)[3]), \
          "r"(b0), "r"(b1))

#define CP16(dst, src) \
    asm volatile("cp.async.ca.shared.global [%0], [%1], 16;" \
                 :: "r"(dst), "l"(src) : "memory")
#define CP_COMMIT() asm volatile("cp.async.commit_group;" ::: "memory")
#define CP_WAIT0()  asm volatile("cp.async.wait_group 0;" ::: "memory")

__device__ __forceinline__ uint32_t packh2(__half a, __half b) {
    __half2 t = __halves2half2(a, b);
    return *(uint32_t*)&t;
}
__device__ __forceinline__ void split_pair(float f0, float f1,
                                           uint32_t& hp, uint32_t& lp) {
    __half h0 = __float2half_rn(f0), h1 = __float2half_rn(f1);
    __half l0 = __float2half_rn(f0 - __half2float(h0));
    __half l1 = __float2half_rn(f1 - __half2float(h1));
    hp = packh2(h0, h1); lp = packh2(l0, l1);
}

// ---------------- elementwise split: fp32 -> hi/lo fp16 planes -------------
__global__ void split_kernel(const float* __restrict__ in,
                             __half* __restrict__ hi, __half* __restrict__ lo,
                             int n4)
{
    int i = blockIdx.x * blockDim.x + threadIdx.x;
    if (i >= n4) return;
    float4 v = ((const float4*)in)[i];
    uint32_t h01, l01, h23, l23;
    split_pair(v.x, v.y, h01, l01);
    split_pair(v.z, v.w, h23, l23);
    ((uint2*)hi)[i] = make_uint2(h01, h23);
    ((uint2*)lo)[i] = make_uint2(l01, l23);
}

// ---- transpose + split: W[K,N] fp32 -> rows [rowoff..rowoff+C) of planes --
__global__ void wsplit_t_kernel(const float* __restrict__ in,
                                __half* __restrict__ hi, __half* __restrict__ lo,
                                int R, int C, int rowoff)
{
    __shared__ float t[32][33];
    const int bx = blockIdx.x * 32, by = blockIdx.y * 32;
    const int tx = threadIdx.x, ty = threadIdx.y;
#pragma unroll
    for (int j = 0; j < 32; j += 8)
        t[ty + j][tx] = in[(size_t)(by + ty + j) * C + bx + tx];
    __syncthreads();
#pragma unroll
    for (int j = 0; j < 32; j += 8) {
        float f = t[tx][ty + j];
        __half h = __float2half_rn(f);
        size_t o = (size_t)(rowoff + bx + ty + j) * R + by + tx;
        hi[o] = h;
        lo[o] = __float2half_rn(f - __half2float(h));
    }
}

// ---------------- V: split + transpose -> Vt[b][kvh][dim][seq] -------------
__global__ void vsplit_t_kernel()
{
    __shared__ float t[32][33];
    const int bkv = blockIdx.z;
    const int b = bkv >> 3, kvh = bkv & 7;
    const int s0 = blockIdx.y * 32;
    const int d0 = blockIdx.x * 32;
    const int tx = threadIdx.x, ty = threadIdx.y;
#pragma unroll
    for (int j = 0; j < 32; j += 8)
        t[ty + j][tx] = g_qkv[(size_t)(b * SEQ + s0 + ty + j) * NQKV
                              + D_MODEL + KVD + kvh * HD + d0 + tx];
    __syncthreads();
#pragma unroll
    for (int j = 0; j < 32; j += 8) {
        float f = t[tx][ty + j];
        __half h = __float2half_rn(f);
        size_t o = ((size_t)(bkv * HD) + d0 + ty + j) * SEQ + s0 + tx;
        g_vth[o] = h;
        g_vtl[o] = __float2half_rn(f - __half2float(h));
    }
}

// ---------------- RoPE + RMSNorm from fused buffer, writes hi/lo planes ----
__global__ void rope_rms_split_kernel(int colbase,
                                      __half* __restrict__ hi, __half* __restrict__ lo,
                                      const float* __restrict__ cosp,
                                      const float* __restrict__ sinp,
                                      int nheads)
{
    int gw = (blockIdx.x * blockDim.x + threadIdx.x) >> 5;
    int lane = threadIdx.x & 31;
    int total = TOK * nheads;
    if (gw >= total) return;
    int tok = gw / nheads;
    int hd = gw % nheads;
    int l = tok % SEQ;

    const float* p = g_qkv + (size_t)tok * NQKV + colbase + hd * HD;
    float x1 = p[lane];
    float x2 = p[lane + 32];
    float c = cosp[l * 32 + lane];
    float s = sinp[l * 32 + lane];
    float o1 = x1 * c - x2 * s;
    float o2 = x2 * c + x1 * s;
    float ss = o1 * o1 + o2 * o2;
#pragma unroll
    for (int off = 16; off > 0; off >>= 1)
        ss += __shfl_xor_sync(0xffffffffu, ss, off);
    float r = rsqrtf(ss * (1.0f / 64.0f) + 1e-6f);
    o1 *= r; o2 *= r;
    __half h1 = __float2half_rn(o1), h2 = __float2half_rn(o2);
    hi[(size_t)gw * HD + lane] = h1;
    hi[(size_t)gw * HD + lane + 32] = h2;
    lo[(size_t)gw * HD + lane] = __float2half_rn(o1 - __half2float(h1));
    lo[(size_t)gw * HD + lane + 32] = __float2half_rn(o2 - __half2float(h2));
}

// ======================= 3xFP16 GEMM, cp.async pipeline (R9) ===============
#define GBM 128
#define GBN 128
#define GBK 32
#define APL 8192
#define OFF_AHI 0
#define OFF_ALO (APL)
#define OFF_BHI (2 * APL)
#define OFF_BLO (3 * APL)
#define BUFSZ (4 * APL)                // 32 KB / stage
#define GEMM_SMEM (2 * BUFSZ)          // 64 KB

__global__ __launch_bounds__(256, 2)
void gemm_mma_kernel(const __half* __restrict__ Ah, const __half* __restrict__ Al,
                     const __half* __restrict__ Bh, const __half* __restrict__ Bl,
                     float* __restrict__ C, int M, int N, int K)
{
    extern __shared__ char sm[];
    const uint32_t sb = smem_u32(sm);
    const int tid = threadIdx.x;
    const int wid = tid >> 5, lane = tid & 31;
    const int m0 = blockIdx.y * GBM;
    const int n0 = blockIdx.x * GBN;
    const int wm = wid & 3;
    const int wn = wid >> 2;

    const __half* srcs[8];
    uint32_t dsts[8];
#pragma unroll
    for (int i = 0; i < 8; i++) {
        int gidx = tid + i * 256;
        int plane = gidx >> 9;
        int c = gidx & 511;
        int r = c >> 2, q = c & 3;
        const __half* base = (plane == 0) ? Ah : (plane == 1) ? Al
                           : (plane == 2) ? Bh : Bl;
        int row = (plane < 2 ? m0 : n0) + r;
        srcs[i] = base + (size_t)row * K + q * 8;
        dsts[i] = (uint32_t)(plane * APL) + SWZ64((uint32_t)(r * 64 + q * 16));
    }

    const int arowl = lane & 15;
    const int ca = lane >> 4;
    uint32_t a_rb[2]; int a_rx[2];
#pragma unroll
    for (int mi = 0; mi < 2; mi++) {
        int r = wm * 32 + mi * 16 + arowl;
        a_rb[mi] = (uint32_t)(r * 64); a_rx[mi] = (r >> 1) & 3;
    }
    const int lrowb = (lane & 7) + ((lane >> 4) << 3);
    const int cb = (lane >> 3) & 1;
    uint32_t b_rb[4]; int b_rx[4];
#pragma unroll
    for (int bi = 0; bi < 4; bi++) {
        int r = wn * 64 + bi * 16 + lrowb;
        b_rb[bi] = (uint32_t)(r * 64); b_rx[bi] = (r >> 1) & 3;
    }

    float acc[2][8][4];
#pragma unroll
    for (int mi = 0; mi < 2; mi++)
#pragma unroll
        for (int ni = 0; ni < 8; ni++)
#pragma unroll
            for (int j = 0; j < 4; j++) acc[mi][ni][j] = 0.0f;

    // prologue: stage 0
#pragma unroll
    for (int i = 0; i < 8; i++) CP16(sb + dsts[i], srcs[i]);
    CP_COMMIT();
    CP_WAIT0();
    __syncthreads();

    const int S = K / GBK;
    for (int s = 0; s < S; s++) {
        const uint32_t base = sb + (uint32_t)(s & 1) * BUFSZ;

        if (s + 1 < S) {
            const uint32_t nb = (uint32_t)((s + 1) & 1) * BUFSZ;
            const int k0 = (s + 1) * GBK;
#pragma unroll
            for (int i = 0; i < 8; i++) CP16(sb + nb + dsts[i], srcs[i] + k0);
            CP_COMMIT();
        }

#pragma unroll
        for (int ks = 0; ks < 2; ks++) {
            uint32_t ah[2][4], al[2][4];
#pragma unroll
            for (int mi = 0; mi < 2; mi++) {
                uint32_t off = a_rb[mi] + (uint32_t)((((ks * 2 + ca) ^ a_rx[mi])) << 4);
                LDSM4(ah[mi], base + OFF_AHI + off);
                LDSM4(al[mi], base + OFF_ALO + off);
            }
#pragma unroll
            for (int nt = 0; nt < 4; nt++) {
                uint32_t bh[4], bl[4];
                uint32_t off = b_rb[nt] + (uint32_t)((((ks * 2 + cb) ^ b_rx[nt])) << 4);
                LDSM4(bh, base + OFF_BHI + off);
                LDSM4(bl, base + OFF_BLO + off);
#pragma unroll
                for (int j = 0; j < 2; j++) {
                    int ni = nt * 2 + j;
#pragma unroll
                    for (int mi = 0; mi < 2; mi++) {
                        MMA_F16(acc[mi][ni], ah[mi], bh[j * 2], bh[j * 2 + 1]);
                        MMA_F16(acc[mi][ni], ah[mi], bl[j * 2], bl[j * 2 + 1]);
                        MMA_F16(acc[mi][ni], al[mi], bh[j * 2], bh[j * 2 + 1]);
                    }
                }
            }
        }

        if (s + 1 < S) {
            CP_WAIT0();
            __syncthreads();
        }
    }

#pragma unroll
    for (int mi = 0; mi < 2; mi++)
#pragma unroll
        for (int ni = 0; ni < 8; ni++) {
            int row = m0 + wm * 32 + mi * 16 + (lane >> 2);
            int col = n0 + wn * 64 + ni * 8 + (lane & 3) * 2;
            *(float2*)(C + (size_t)row * N + col) =
                make_float2(acc[mi][ni][0], acc[mi][ni][1]);
            *(float2*)(C + (size_t)(row + 8) * N + col) =
                make_float2(acc[mi][ni][2], acc[mi][ni][3]);
        }
}

// =============== Flash attention: R9 (serial K/V load, P in registers) =====
#define QHI_B 0u
#define QLO_B 16384u
#define KHI_B 32768u
#define VHI_B 49152u        // KHI 32768, KLO 40960, VHI 49152, VLO 57344
#define ATTN_SMEM 65536     // 64 KB -> 2 CTAs/SM

__global__ __launch_bounds__(256, 2) void attn_mma_kernel()
{
    extern __shared__ float smf[];
    const uint32_t sb = smem_u32(smf);
    const int qt = (int)gridDim.x - 1 - (int)blockIdx.x;
    const int h = blockIdx.y, b = blockIdx.z;
    const int kvh = h >> 2;
    const int tid = threadIdx.x;
    const int warp = tid >> 5, lane = tid & 31;
    const int q0 = qt * 128;

    // ---- Q planes ----
#pragma unroll
    for (int i = 0; i < 8; i++) {
        int gidx = tid + i * 256;
        int plane = gidx >> 10;
        int c = gidx & 1023;
        int r = c >> 3, q = c & 7;
        const __half* src = (plane ? g_ql : g_qh)
            + (((size_t)(b * SEQ + q0 + r) * NH + h) << 6) + q * 8;
        CP16(sb + QHI_B + (uint32_t)plane * 16384u + SWZ((uint32_t)(r * 128 + q * 16)), src);
    }
    CP_COMMIT();

    // K/V per-tile cp.async slots
    const __half* kv_src[8];
    uint32_t kv_dst[8];
    int kv_step[8];
#pragma unroll
    for (int i = 0; i < 8; i++) {
        int gidx = tid + i * 256;
        int plane = gidx >> 9;
        int c = gidx & 511;
        int r = c >> 3, q = c & 7;
        if (plane < 2) {
            kv_src[i] = (plane ? g_kl : g_kh)
                + (((size_t)(b * SEQ + r) * NKV + kvh) << 6) + q * 8;
            kv_step[i] = NKV * HD;
        } else {
            kv_src[i] = ((plane == 3) ? g_vtl : g_vth)
                + ((size_t)((b * NKV + kvh) * HD) + r) * SEQ + q * 8;
            kv_step[i] = 1;
        }
        kv_dst[i] = KHI_B + (uint32_t)plane * 8192u + SWZ((uint32_t)(r * 128 + q * 16));
    }

    // fragment geometry
    const int arowl = lane & 15;
    const int ca = lane >> 4;
    const int lrowb = (lane & 7) + ((lane >> 4) << 3);
    const int cb = (lane >> 3) & 1;
    const int ar = warp * 16 + arowl;
    const uint32_t a_rb = (uint32_t)(ar * 128);
    const int a_rx = ar & 7;
    uint32_t b_rb[4]; int b_rx[4];
#pragma unroll
    for (int bi = 0; bi < 4; bi++) {
        int r = bi * 16 + lrowb;
        b_rb[bi] = (uint32_t)(r * 128); b_rx[bi] = r & 7;
    }

    float m0 = -1e30f, m1 = -1e30f, l0 = 0.f, l1 = 0.f;
    float oacc[8][4];
#pragma unroll
    for (int nt = 0; nt < 8; nt++)
#pragma unroll
        for (int j = 0; j < 4; j++) oacc[nt][j] = 0.f;

    const int rloc = lane >> 2;
    const int qrow0 = q0 + warp * 16 + rloc;
    const int qrow1 = qrow0 + 8;
    const int ktmax = 2 * qt + 1;

    for (int kt = 0; kt <= ktmax; kt++) {
        const int k0 = kt * 64;
        __syncthreads();
#pragma unroll
        for (int i = 0; i < 8; i++)
            CP16(sb + kv_dst[i], kv_src[i] + (size_t)k0 * kv_step[i]);
        CP_COMMIT();
        CP_WAIT0();
        __syncthreads();

        // ---- S = Q @ K^T ----
        float sacc[8][4];
#pragma unroll
        for (int nt = 0; nt < 8; nt++)
#pragma unroll
            for (int j = 0; j < 4; j++) sacc[nt][j] = 0.f;

#pragma unroll
        for (int ks = 0; ks < 4; ks++) {
            uint32_t qh[4], ql[4];
            uint32_t aoff = a_rb + (uint32_t)((((ks * 2 + ca) ^ a_rx)) << 4);
            LDSM4(qh, sb + QHI_B + aoff);
            LDSM4(ql, sb + QLO_B + aoff);
#pragma unroll
            for (int nt = 0; nt < 4; nt++) {
                uint32_t kh[4], kl[4];
                uint32_t boff = b_rb[nt] + (uint32_t)((((ks * 2 + cb) ^ b_rx[nt])) << 4);
                LDSM4(kh, sb + KHI_B + boff);
                LDSM4(kl, sb + KHI_B + 8192u + boff);
#pragma unroll
                for (int j = 0; j < 2; j++) {
                    int ni = nt * 2 + j;
                    MMA_F16(sacc[ni], qh, kh[j * 2], kh[j * 2 + 1]);
                    MMA_F16(sacc[ni], qh, kl[j * 2], kl[j * 2 + 1]);
                    MMA_F16(sacc[ni], ql, kh[j * 2], kh[j * 2 + 1]);
                }
            }
        }

        // ---- online softmax ----
        const bool domask = (k0 + 63 > q0);
#pragma unroll
        for (int nt = 0; nt < 8; nt++) {
            int keyb = k0 + nt * 8 + (lane & 3) * 2;
#pragma unroll
            for (int j = 0; j < 4; j++) {
                float s = sacc[nt][j] * 0.125f;
                if (domask) {
                    int key = keyb + (j & 1);
                    int qq = (j < 2) ? qrow0 : qrow1;
                    if (key > qq) s = -1e30f;
                }
                sacc[nt][j] = s;
            }
        }
        float mx0 = -1e30f, mx1 = -1e30f;
#pragma unroll
        for (int nt = 0; nt < 8; nt++) {
            mx0 = fmaxf(mx0, fmaxf(sacc[nt][0], sacc[nt][1]));
            mx1 = fmaxf(mx1, fmaxf(sacc[nt][2], sacc[nt][3]));
        }
        mx0 = fmaxf(mx0, __shfl_xor_sync(0xffffffffu, mx0, 1));
        mx0 = fmaxf(mx0, __shfl_xor_sync(0xffffffffu, mx0, 2));
        mx1 = fmaxf(mx1, __shfl_xor_sync(0xffffffffu, mx1, 1));
        mx1 = fmaxf(mx1, __shfl_xor_sync(0xffffffffu, mx1, 2));
        float nm0 = fmaxf(m0, mx0), nm1 = fmaxf(m1, mx1);
        float c0 = __expf(m0 - nm0), c1 = __expf(m1 - nm1);
        m0 = nm0; m1 = nm1;
        float rs0 = 0.f, rs1 = 0.f;
#pragma unroll
        for (int nt = 0; nt < 8; nt++) {
            float p0 = __expf(sacc[nt][0] - nm0);
            float p1 = __expf(sacc[nt][1] - nm0);
            float p2 = __expf(sacc[nt][2] - nm1);
            float p3 = __expf(sacc[nt][3] - nm1);
            sacc[nt][0] = p0; sacc[nt][1] = p1; sacc[nt][2] = p2; sacc[nt][3] = p3;
            rs0 += p0 + p1; rs1 += p2 + p3;
        }
        rs0 += __shfl_xor_sync(0xffffffffu, rs0, 1);
        rs0 += __shfl_xor_sync(0xffffffffu, rs0, 2);
        rs1 += __shfl_xor_sync(0xffffffffu, rs1, 1);
        rs1 += __shfl_xor_sync(0xffffffffu, rs1, 2);
        l0 = l0 * c0 + rs0;
        l1 = l1 * c1 + rs1;
#pragma unroll
        for (int nt = 0; nt < 8; nt++) {
            oacc[nt][0] *= c0; oacc[nt][1] *= c0;
            oacc[nt][2] *= c1; oacc[nt][3] *= c1;
        }

        // ---- O += P @ V  (P packed from registers, proven) ----
#pragma unroll
        for (int ks = 0; ks < 4; ks++) {
            uint32_t pa[4], pb[4];
            split_pair(sacc[2 * ks][0],     sacc[2 * ks][1],     pa[0], pb[0]);
            split_pair(sacc[2 * ks][2],     sacc[2 * ks][3],     pa[1], pb[1]);
            split_pair(sacc[2 * ks + 1][0], sacc[2 * ks + 1][1], pa[2], pb[2]);
            split_pair(sacc[2 * ks + 1][2], sacc[2 * ks + 1][3], pa[3], pb[3]);
#pragma unroll
            for (int nt = 0; nt < 4; nt++) {
                uint32_t vh[4], vl[4];
                uint32_t boff = b_rb[nt] + (uint32_t)((((ks * 2 + cb) ^ b_rx[nt])) << 4);
                LDSM4(vh, sb + VHI_B + boff);
                LDSM4(vl, sb + VHI_B + 8192u + boff);
#pragma unroll
                for (int j = 0; j < 2; j++) {
                    int ni = nt * 2 + j;
                    MMA_F16(oacc[ni], pa, vh[j * 2], vh[j * 2 + 1]);
                    MMA_F16(oacc[ni], pa, vl[j * 2], vl[j * 2 + 1]);
                    MMA_F16(oacc[ni], pb, vh[j * 2], vh[j * 2 + 1]);
                }
            }
        }
    }

    // ---- epilogue: normalize + split into o planes ----
    float inv0 = 1.0f / l0, inv1 = 1.0f / l1;
    size_t o0 = (((size_t)(b * SEQ + qrow0) * NH + h) << 6);
    size_t o1 = (((size_t)(b * SEQ + qrow1) * NH + h) << 6);
#pragma unroll
    for (int nt = 0; nt < 8; nt++) {
        int dim = nt * 8 + (lane & 3) * 2;
        uint32_t hp, lp;
        split_pair(oacc[nt][0] * inv0, oacc[nt][1] * inv0, hp, lp);
        *(uint32_t*)(g_oh + o0 + dim) = hp;
        *(uint32_t*)(g_ol + o0 + dim) = lp;
        split_pair(oacc[nt][2] * inv1, oacc[nt][3] * inv1, hp, lp);
        *(uint32_t*)(g_oh + o1 + dim) = hp;
        *(uint32_t*)(g_ol + o1 + dim) = lp;
    }
}

// ---------------- launch ---------------------------------------------------
extern "C" void kernel_launch(void* const* d_in, const int* in_sizes, int n_in,
                              void* d_out, int out_size)
{
    const float* x    = (const float*)d_in[0];
    const float* cosp = (const float*)d_in[1];
    const float* sinp = (const float*)d_in[2];
    const float* Wq   = (const float*)d_in[3];
    const float* Wk   = (const float*)d_in[4];
    const float* Wv   = (const float*)d_in[5];
    const float* Wo   = (const float*)d_in[6];
    float* out = (float*)d_out;

    float* qkv;
    __half *xh, *xl, *wh, *wl, *woth, *wotl;
    __half *qh, *ql, *kh, *kl, *oh, *ol;
    cudaGetSymbolAddress((void**)&qkv, g_qkv);
    cudaGetSymbolAddress((void**)&xh, g_xh);
    cudaGetSymbolAddress((void**)&xl, g_xl);
    cudaGetSymbolAddress((void**)&wh, g_wh);
    cudaGetSymbolAddress((void**)&wl, g_wl);
    cudaGetSymbolAddress((void**)&woth, g_woth);
    cudaGetSymbolAddress((void**)&wotl, g_wotl);
    cudaGetSymbolAddress((void**)&qh, g_qh);
    cudaGetSymbolAddress((void**)&ql, g_ql);
    cudaGetSymbolAddress((void**)&kh, g_kh);
    cudaGetSymbolAddress((void**)&kl, g_kl);
    cudaGetSymbolAddress((void**)&oh, g_oh);
    cudaGetSymbolAddress((void**)&ol, g_ol);

    cudaFuncSetAttribute(gemm_mma_kernel,
                         cudaFuncAttributeMaxDynamicSharedMemorySize, GEMM_SMEM);
    cudaFuncSetAttribute(attn_mma_kernel,
                         cudaFuncAttributeMaxDynamicSharedMemorySize, ATTN_SMEM);

    dim3 tb(32, 8);
    // one-time splits (weights go into concatenated planes)
    split_kernel<<<(TOK * D_MODEL / 4 + 255) / 256, 256>>>(x, xh, xl, TOK * D_MODEL / 4);
    wsplit_t_kernel<<<dim3(D_MODEL / 32, D_MODEL / 32), tb>>>(Wq, wh, wl, D_MODEL, D_MODEL, 0);
    wsplit_t_kernel<<<dim3(KVD / 32, D_MODEL / 32), tb>>>(Wk, wh, wl, D_MODEL, KVD, D_MODEL);
    wsplit_t_kernel<<<dim3(KVD / 32, D_MODEL / 32), tb>>>(Wv, wh, wl, D_MODEL, KVD, D_MODEL + KVD);
    wsplit_t_kernel<<<dim3(D_MODEL / 32, D_MODEL / 32), tb>>>(Wo, woth, wotl, D_MODEL, D_MODEL, 0);

    // fused Q|K|V projection: [TOK, 3072]
    gemm_mma_kernel<<<dim3(NQKV / GBN, TOK / GBM), 256, GEMM_SMEM>>>(
        xh, xl, wh, wl, qkv, TOK, NQKV, D_MODEL);

    rope_rms_split_kernel<<<(TOK * NH) / 8, 256>>>(0, qh, ql, cosp, sinp, NH);
    rope_rms_split_kernel<<<(TOK * NKV) / 8, 256>>>(D_MODEL, kh, kl, cosp, sinp, NKV);
    vsplit_t_kernel<<<dim3(HD / 32, SEQ / 32, BATCH * NKV), tb>>>();

    attn_mma_kernel<<<dim3(SEQ / 128, NH, BATCH), 256, ATTN_SMEM>>>();

    gemm_mma_kernel<<<dim3(D_MODEL / GBN, TOK / GBM), 256, GEMM_SMEM>>>(
        oh, ol, woth, wotl, out, TOK, D_MODEL, D_MODEL);
}

// round 12
// speedup vs baseline: 1.4526x; 1.4526x over previous
#include <cuda_runtime.h>
#include <cuda_fp16.h>
#include <math.h>
#include <stdint.h>

#define D_MODEL 2048
#define NH 32
#define NKV 8
#define HD 64
#define BATCH 2
#define SEQ 2048
#define TOK (BATCH * SEQ)   // 4096
#define KVD (NKV * HD)      // 512

// ---------------- scratch (device globals; no allocation allowed) ----------
__device__ float  g_q[(size_t)TOK * NH * HD];
__device__ float  g_k[(size_t)TOK * NKV * HD];
__device__ float  g_v[(size_t)TOK * NKV * HD];
__device__ __half g_xh[(size_t)TOK * D_MODEL];
__device__ __half g_xl[(size_t)TOK * D_MODEL];
__device__ __half g_wqth[(size_t)D_MODEL * D_MODEL];
__device__ __half g_wqtl[(size_t)D_MODEL * D_MODEL];
__device__ __half g_wkth[(size_t)KVD * D_MODEL];
__device__ __half g_wktl[(size_t)KVD * D_MODEL];
__device__ __half g_wvth[(size_t)KVD * D_MODEL];
__device__ __half g_wvtl[(size_t)KVD * D_MODEL];
__device__ __half g_woth[(size_t)D_MODEL * D_MODEL];
__device__ __half g_wotl[(size_t)D_MODEL * D_MODEL];
__device__ __half g_qh[(size_t)TOK * NH * HD];
__device__ __half g_ql[(size_t)TOK * NH * HD];
__device__ __half g_kh[(size_t)TOK * NKV * HD];
__device__ __half g_kl[(size_t)TOK * NKV * HD];
__device__ __half g_vth[(size_t)BATCH * NKV * HD * SEQ];
__device__ __half g_vtl[(size_t)BATCH * NKV * HD * SEQ];
__device__ __half g_oh[(size_t)TOK * NH * HD];
__device__ __half g_ol[(size_t)TOK * NH * HD];

// ======================= helpers (portable PTX only) ========================
__device__ __forceinline__ uint32_t smem_u32(const void* p) {
    uint32_t a;
    asm("{ .reg .u64 t; cvta.to.shared.u64 t, %1; cvt.u32.u64 %0, t; }"
        : "=r"(a) : "l"(p));
    return a;
}
#define SWZ(o)   ((o) ^ (((o) >> 3) & 0x70))
#define SWZ64(o) ((o) ^ (((o) >> 3) & 0x30))

#define LDSM4(r, a) \
    asm volatile("ldmatrix.sync.aligned.m8n8.x4.shared.b16 {%0,%1,%2,%3}, [%4];" \
        : "=r"((r)[0]), "=r"((r)[1]), "=r"((r)[2]), "=r"((r)[3]) : "r"(a))

#define MMA_F16(c, a, b0, b1) \
    asm volatile("mma.sync.aligned.m16n8k16.row.col.f32.f16.f16.f32 " \
        "{%0,%1,%2,%3}, {%4,%5,%6,%7}, {%8,%9}, {%0,%1,%2,%3};" \
        : "+f"((c)[0]), "+f"((c)[1]), "+f"((c)[2]), "+f"((c)[3]) \
        : "r"((a)[0]), "r"((a)[1]), "r"((a)[2]), "r"((a)[3]), \
          "r"(b0), "r"(b1))

#define CP16(dst, src) \
    asm volatile("cp.async.ca.shared.global [%0], [%1], 16;" \
                 :: "r"(dst), "l"(src) : "memory")
#define CP_COMMIT() asm volatile("cp.async.commit_group;" ::: "memory")
#define CP_WAIT0()  asm volatile("cp.async.wait_group 0;" ::: "memory")

__device__ __forceinline__ uint32_t packh2(__half a, __half b) {
    __half2 t = __halves2half2(a, b);
    return *(uint32_t*)&t;
}
__device__ __forceinline__ void split_pair(float f0, float f1,
                                           uint32_t& hp, uint32_t& lp) {
    __half h0 = __float2half_rn(f0), h1 = __float2half_rn(f1);
    __half l0 = __float2half_rn(f0 - __half2float(h0));
    __half l1 = __float2half_rn(f1 - __half2float(h1));
    hp = packh2(h0, h1); lp = packh2(l0, l1);
}

// ---------------- elementwise split: fp32 -> hi/lo fp16 planes -------------
__global__ void split_kernel(const float* __restrict__ in,
                             __half* __restrict__ hi, __half* __restrict__ lo,
                             int n4)
{
    int i = blockIdx.x * blockDim.x + threadIdx.x;
    if (i >= n4) return;
    float4 v = ((const float4*)in)[i];
    uint32_t h01, l01, h23, l23;
    split_pair(v.x, v.y, h01, l01);
    split_pair(v.z, v.w, h23, l23);
    ((uint2*)hi)[i] = make_uint2(h01, h23);
    ((uint2*)lo)[i] = make_uint2(l01, l23);
}

// ---------------- transpose + split: W[K,N] fp32 -> Wt hi/lo [N,K] half ----
__global__ void wsplit_t_kernel(const float* __restrict__ in,
                                __half* __restrict__ hi, __half* __restrict__ lo,
                                int R, int C)
{
    __shared__ float t[32][33];
    const int bx = blockIdx.x * 32, by = blockIdx.y * 32;
    const int tx = threadIdx.x, ty = threadIdx.y;
#pragma unroll
    for (int j = 0; j < 32; j += 8)
        t[ty + j][tx] = in[(size_t)(by + ty + j) * C + bx + tx];
    __syncthreads();
#pragma unroll
    for (int j = 0; j < 32; j += 8) {
        float f = t[tx][ty + j];
        __half h = __float2half_rn(f);
        size_t o = (size_t)(bx + ty + j) * R + by + tx;
        hi[o] = h;
        lo[o] = __float2half_rn(f - __half2float(h));
    }
}

// ---------------- V: split + transpose -> Vt[b][kvh][dim][seq] -------------
__global__ void vsplit_t_kernel()
{
    __shared__ float t[32][33];
    const int bkv = blockIdx.z;
    const int b = bkv >> 3, kvh = bkv & 7;
    const int s0 = blockIdx.y * 32;
    const int d0 = blockIdx.x * 32;
    const int tx = threadIdx.x, ty = threadIdx.y;
#pragma unroll
    for (int j = 0; j < 32; j += 8)
        t[ty + j][tx] = g_v[(((size_t)(b * SEQ + s0 + ty + j) * NKV + kvh) << 6) + d0 + tx];
    __syncthreads();
#pragma unroll
    for (int j = 0; j < 32; j += 8) {
        float f = t[tx][ty + j];
        __half h = __float2half_rn(f);
        size_t o = ((size_t)(bkv * HD) + d0 + ty + j) * SEQ + s0 + tx;
        g_vth[o] = h;
        g_vtl[o] = __float2half_rn(f - __half2float(h));
    }
}

// ---------------- RoPE + RMSNorm, writes hi/lo fp16 planes -----------------
__global__ void rope_rms_split_kernel(const float* __restrict__ src,
                                      __half* __restrict__ hi, __half* __restrict__ lo,
                                      const float* __restrict__ cosp,
                                      const float* __restrict__ sinp,
                                      int nheads)
{
    int gw = (blockIdx.x * blockDim.x + threadIdx.x) >> 5;
    int lane = threadIdx.x & 31;
    int total = TOK * nheads;
    if (gw >= total) return;
    int tok = gw / nheads;
    int l = tok % SEQ;

    const float* p = src + (size_t)gw * HD;
    float x1 = p[lane];
    float x2 = p[lane + 32];
    float c = cosp[l * 32 + lane];
    float s = sinp[l * 32 + lane];
    float o1 = x1 * c - x2 * s;
    float o2 = x2 * c + x1 * s;
    float ss = o1 * o1 + o2 * o2;
#pragma unroll
    for (int off = 16; off > 0; off >>= 1)
        ss += __shfl_xor_sync(0xffffffffu, ss, off);
    float r = rsqrtf(ss * (1.0f / 64.0f) + 1e-6f);
    o1 *= r; o2 *= r;
    __half h1 = __float2half_rn(o1), h2 = __float2half_rn(o2);
    hi[(size_t)gw * HD + lane] = h1;
    hi[(size_t)gw * HD + lane + 32] = h2;
    lo[(size_t)gw * HD + lane] = __float2half_rn(o1 - __half2float(h1));
    lo[(size_t)gw * HD + lane + 32] = __float2half_rn(o2 - __half2float(h2));
}

// ======================= 3xFP16 GEMM, cp.async pipeline (R9) ===============
#define GBM 128
#define GBN 128
#define GBK 32
#define APL 8192
#define OFF_AHI 0
#define OFF_ALO (APL)
#define OFF_BHI (2 * APL)
#define OFF_BLO (3 * APL)
#define BUFSZ (4 * APL)                // 32 KB / stage
#define GEMM_SMEM (2 * BUFSZ)          // 64 KB

__global__ __launch_bounds__(256, 2)
void gemm_mma_kernel(const __half* __restrict__ Ah, const __half* __restrict__ Al,
                     const __half* __restrict__ Bh, const __half* __restrict__ Bl,
                     float* __restrict__ C, int M, int N, int K)
{
    extern __shared__ char sm[];
    const uint32_t sb = smem_u32(sm);
    const int tid = threadIdx.x;
    const int wid = tid >> 5, lane = tid & 31;
    const int m0 = blockIdx.y * GBM;
    const int n0 = blockIdx.x * GBN;
    const int wm = wid & 3;
    const int wn = wid >> 2;

    const __half* srcs[8];
    uint32_t dsts[8];
#pragma unroll
    for (int i = 0; i < 8; i++) {
        int gidx = tid + i * 256;
        int plane = gidx >> 9;
        int c = gidx & 511;
        int r = c >> 2, q = c & 3;
        const __half* base = (plane == 0) ? Ah : (plane == 1) ? Al
                           : (plane == 2) ? Bh : Bl;
        int row = (plane < 2 ? m0 : n0) + r;
        srcs[i] = base + (size_t)row * K + q * 8;
        dsts[i] = (uint32_t)(plane * APL) + SWZ64((uint32_t)(r * 64 + q * 16));
    }

    const int arowl = lane & 15;
    const int ca = lane >> 4;
    uint32_t a_rb[2]; int a_rx[2];
#pragma unroll
    for (int mi = 0; mi < 2; mi++) {
        int r = wm * 32 + mi * 16 + arowl;
        a_rb[mi] = (uint32_t)(r * 64); a_rx[mi] = (r >> 1) & 3;
    }
    const int lrowb = (lane & 7) + ((lane >> 4) << 3);
    const int cb = (lane >> 3) & 1;
    uint32_t b_rb[4]; int b_rx[4];
#pragma unroll
    for (int bi = 0; bi < 4; bi++) {
        int r = wn * 64 + bi * 16 + lrowb;
        b_rb[bi] = (uint32_t)(r * 64); b_rx[bi] = (r >> 1) & 3;
    }

    float acc[2][8][4];
#pragma unroll
    for (int mi = 0; mi < 2; mi++)
#pragma unroll
        for (int ni = 0; ni < 8; ni++)
#pragma unroll
            for (int j = 0; j < 4; j++) acc[mi][ni][j] = 0.0f;

    // prologue: stage 0
#pragma unroll
    for (int i = 0; i < 8; i++) CP16(sb + dsts[i], srcs[i]);
    CP_COMMIT();
    CP_WAIT0();
    __syncthreads();

    const int S = K / GBK;
    for (int s = 0; s < S; s++) {
        const uint32_t base = sb + (uint32_t)(s & 1) * BUFSZ;

        if (s + 1 < S) {
            const uint32_t nb = (uint32_t)((s + 1) & 1) * BUFSZ;
            const int k0 = (s + 1) * GBK;
#pragma unroll
            for (int i = 0; i < 8; i++) CP16(sb + nb + dsts[i], srcs[i] + k0);
            CP_COMMIT();
        }

#pragma unroll
        for (int ks = 0; ks < 2; ks++) {
            uint32_t ah[2][4], al[2][4];
#pragma unroll
            for (int mi = 0; mi < 2; mi++) {
                uint32_t off = a_rb[mi] + (uint32_t)((((ks * 2 + ca) ^ a_rx[mi])) << 4);
                LDSM4(ah[mi], base + OFF_AHI + off);
                LDSM4(al[mi], base + OFF_ALO + off);
            }
#pragma unroll
            for (int nt = 0; nt < 4; nt++) {
                uint32_t bh[4], bl[4];
                uint32_t off = b_rb[nt] + (uint32_t)((((ks * 2 + cb) ^ b_rx[nt])) << 4);
                LDSM4(bh, base + OFF_BHI + off);
                LDSM4(bl, base + OFF_BLO + off);
#pragma unroll
                for (int j = 0; j < 2; j++) {
                    int ni = nt * 2 + j;
#pragma unroll
                    for (int mi = 0; mi < 2; mi++) {
                        MMA_F16(acc[mi][ni], ah[mi], bh[j * 2], bh[j * 2 + 1]);
                        MMA_F16(acc[mi][ni], ah[mi], bl[j * 2], bl[j * 2 + 1]);
                        MMA_F16(acc[mi][ni], al[mi], bh[j * 2], bh[j * 2 + 1]);
                    }
                }
            }
        }

        if (s + 1 < S) {
            CP_WAIT0();
            __syncthreads();
        }
    }

#pragma unroll
    for (int mi = 0; mi < 2; mi++)
#pragma unroll
        for (int ni = 0; ni < 8; ni++) {
            int row = m0 + wm * 32 + mi * 16 + (lane >> 2);
            int col = n0 + wn * 64 + ni * 8 + (lane & 3) * 2;
            *(float2*)(C + (size_t)row * N + col) =
                make_float2(acc[mi][ni][0], acc[mi][ni][1]);
            *(float2*)(C + (size_t)(row + 8) * N + col) =
                make_float2(acc[mi][ni][2], acc[mi][ni][3]);
        }
}

// =============== Flash attention: R9 + Q fragments hoisted to registers ====
#define QHI_B 0u
#define QLO_B 16384u
#define KHI_B 32768u
#define VHI_B 49152u        // KHI 32768, KLO 40960, VHI 49152, VLO 57344
#define ATTN_SMEM 65536     // 64 KB -> 2 CTAs/SM

__global__ __launch_bounds__(256, 2) void attn_mma_kernel()
{
    extern __shared__ float smf[];
    const uint32_t sb = smem_u32(smf);
    const int qt = (int)gridDim.x - 1 - (int)blockIdx.x;
    const int h = blockIdx.y, b = blockIdx.z;
    const int kvh = h >> 2;
    const int tid = threadIdx.x;
    const int warp = tid >> 5, lane = tid & 31;
    const int q0 = qt * 128;

    // ---- Q planes via cp.async ----
#pragma unroll
    for (int i = 0; i < 8; i++) {
        int gidx = tid + i * 256;
        int plane = gidx >> 10;
        int c = gidx & 1023;
        int r = c >> 3, q = c & 7;
        const __half* src = (plane ? g_ql : g_qh)
            + (((size_t)(b * SEQ + q0 + r) * NH + h) << 6) + q * 8;
        CP16(sb + QHI_B + (uint32_t)plane * 16384u + SWZ((uint32_t)(r * 128 + q * 16)), src);
    }
    CP_COMMIT();

    // K/V per-tile cp.async slots
    const __half* kv_src[8];
    uint32_t kv_dst[8];
    int kv_step[8];
#pragma unroll
    for (int i = 0; i < 8; i++) {
        int gidx = tid + i * 256;
        int plane = gidx >> 9;
        int c = gidx & 511;
        int r = c >> 3, q = c & 7;
        if (plane < 2) {
            kv_src[i] = (plane ? g_kl : g_kh)
                + (((size_t)(b * SEQ + r) * NKV + kvh) << 6) + q * 8;
            kv_step[i] = NKV * HD;
        } else {
            kv_src[i] = ((plane == 3) ? g_vtl : g_vth)
                + ((size_t)((b * NKV + kvh) * HD) + r) * SEQ + q * 8;
            kv_step[i] = 1;
        }
        kv_dst[i] = KHI_B + (uint32_t)plane * 8192u + SWZ((uint32_t)(r * 128 + q * 16));
    }

    // fragment geometry
    const int arowl = lane & 15;
    const int ca = lane >> 4;
    const int lrowb = (lane & 7) + ((lane >> 4) << 3);
    const int cb = (lane >> 3) & 1;
    const int ar = warp * 16 + arowl;
    const uint32_t a_rb = (uint32_t)(ar * 128);
    const int a_rx = ar & 7;
    uint32_t b_rb[4]; int b_rx[4];
#pragma unroll
    for (int bi = 0; bi < 4; bi++) {
        int r = bi * 16 + lrowb;
        b_rb[bi] = (uint32_t)(r * 128); b_rx[bi] = r & 7;
    }

    // ---- hoist Q fragments to registers (read smem once, not per tile) ----
    CP_WAIT0();
    __syncthreads();
    uint32_t qfh[4][4], qfl[4][4];
#pragma unroll
    for (int ks = 0; ks < 4; ks++) {
        uint32_t aoff = a_rb + (uint32_t)((((ks * 2 + ca) ^ a_rx)) << 4);
        LDSM4(qfh[ks], sb + QHI_B + aoff);
        LDSM4(qfl[ks], sb + QLO_B + aoff);
    }

    float m0 = -1e30f, m1 = -1e30f, l0 = 0.f, l1 = 0.f;
    float oacc[8][4];
#pragma unroll
    for (int nt = 0; nt < 8; nt++)
#pragma unroll
        for (int j = 0; j < 4; j++) oacc[nt][j] = 0.f;

    const int rloc = lane >> 2;
    const int qrow0 = q0 + warp * 16 + rloc;
    const int qrow1 = qrow0 + 8;
    const int ktmax = 2 * qt + 1;

    for (int kt = 0; kt <= ktmax; kt++) {
        const int k0 = kt * 64;
        __syncthreads();
#pragma unroll
        for (int i = 0; i < 8; i++)
            CP16(sb + kv_dst[i], kv_src[i] + (size_t)k0 * kv_step[i]);
        CP_COMMIT();
        CP_WAIT0();
        __syncthreads();

        // ---- S = Q @ K^T (Q from registers) ----
        float sacc[8][4];
#pragma unroll
        for (int nt = 0; nt < 8; nt++)
#pragma unroll
            for (int j = 0; j < 4; j++) sacc[nt][j] = 0.f;

#pragma unroll
        for (int ks = 0; ks < 4; ks++) {
#pragma unroll
            for (int nt = 0; nt < 4; nt++) {
                uint32_t kh[4], kl[4];
                uint32_t boff = b_rb[nt] + (uint32_t)((((ks * 2 + cb) ^ b_rx[nt])) << 4);
                LDSM4(kh, sb + KHI_B + boff);
                LDSM4(kl, sb + KHI_B + 8192u + boff);
#pragma unroll
                for (int j = 0; j < 2; j++) {
                    int ni = nt * 2 + j;
                    MMA_F16(sacc[ni], qfh[ks], kh[j * 2], kh[j * 2 + 1]);
                    MMA_F16(sacc[ni], qfh[ks], kl[j * 2], kl[j * 2 + 1]);
                    MMA_F16(sacc[ni], qfl[ks], kh[j * 2], kh[j * 2 + 1]);
                }
            }
        }

        // ---- online softmax ----
        const bool domask = (k0 + 63 > q0);
#pragma unroll
        for (int nt = 0; nt < 8; nt++) {
            int keyb = k0 + nt * 8 + (lane & 3) * 2;
#pragma unroll
            for (int j = 0; j < 4; j++) {
                float s = sacc[nt][j] * 0.125f;
                if (domask) {
                    int key = keyb + (j & 1);
                    int qq = (j < 2) ? qrow0 : qrow1;
                    if (key > qq) s = -1e30f;
                }
                sacc[nt][j] = s;
            }
        }
        float mx0 = -1e30f, mx1 = -1e30f;
#pragma unroll
        for (int nt = 0; nt < 8; nt++) {
            mx0 = fmaxf(mx0, fmaxf(sacc[nt][0], sacc[nt][1]));
            mx1 = fmaxf(mx1, fmaxf(sacc[nt][2], sacc[nt][3]));
        }
        mx0 = fmaxf(mx0, __shfl_xor_sync(0xffffffffu, mx0, 1));
        mx0 = fmaxf(mx0, __shfl_xor_sync(0xffffffffu, mx0, 2));
        mx1 = fmaxf(mx1, __shfl_xor_sync(0xffffffffu, mx1, 1));
        mx1 = fmaxf(mx1, __shfl_xor_sync(0xffffffffu, mx1, 2));
        float nm0 = fmaxf(m0, mx0), nm1 = fmaxf(m1, mx1);
        float c0 = __expf(m0 - nm0), c1 = __expf(m1 - nm1);
        m0 = nm0; m1 = nm1;
        float rs0 = 0.f, rs1 = 0.f;
#pragma unroll
        for (int nt = 0; nt < 8; nt++) {
            float p0 = __expf(sacc[nt][0] - nm0);
            float p1 = __expf(sacc[nt][1] - nm0);
            float p2 = __expf(sacc[nt][2] - nm1);
            float p3 = __expf(sacc[nt][3] - nm1);
            sacc[nt][0] = p0; sacc[nt][1] = p1; sacc[nt][2] = p2; sacc[nt][3] = p3;
            rs0 += p0 + p1; rs1 += p2 + p3;
        }
        rs0 += __shfl_xor_sync(0xffffffffu, rs0, 1);
        rs0 += __shfl_xor_sync(0xffffffffu, rs0, 2);
        rs1 += __shfl_xor_sync(0xffffffffu, rs1, 1);
        rs1 += __shfl_xor_sync(0xffffffffu, rs1, 2);
        l0 = l0 * c0 + rs0;
        l1 = l1 * c1 + rs1;
#pragma unroll
        for (int nt = 0; nt < 8; nt++) {
            oacc[nt][0] *= c0; oacc[nt][1] *= c0;
            oacc[nt][2] *= c1; oacc[nt][3] *= c1;
        }

        // ---- O += P @ V  (P packed from registers, proven) ----
#pragma unroll
        for (int ks = 0; ks < 4; ks++) {
            uint32_t pa[4], pb[4];
            split_pair(sacc[2 * ks][0],     sacc[2 * ks][1],     pa[0], pb[0]);
            split_pair(sacc[2 * ks][2],     sacc[2 * ks][3],     pa[1], pb[1]);
            split_pair(sacc[2 * ks + 1][0], sacc[2 * ks + 1][1], pa[2], pb[2]);
            split_pair(sacc[2 * ks + 1][2], sacc[2 * ks + 1][3], pa[3], pb[3]);
#pragma unroll
            for (int nt = 0; nt < 4; nt++) {
                uint32_t vh[4], vl[4];
                uint32_t boff = b_rb[nt] + (uint32_t)((((ks * 2 + cb) ^ b_rx[nt])) << 4);
                LDSM4(vh, sb + VHI_B + boff);
                LDSM4(vl, sb + VHI_B + 8192u + boff);
#pragma unroll
                for (int j = 0; j < 2; j++) {
                    int ni = nt * 2 + j;
                    MMA_F16(oacc[ni], pa, vh[j * 2], vh[j * 2 + 1]);
                    MMA_F16(oacc[ni], pa, vl[j * 2], vl[j * 2 + 1]);
                    MMA_F16(oacc[ni], pb, vh[j * 2], vh[j * 2 + 1]);
                }
            }
        }
    }

    // ---- epilogue: normalize + split into o planes ----
    float inv0 = 1.0f / l0, inv1 = 1.0f / l1;
    size_t o0 = (((size_t)(b * SEQ + qrow0) * NH + h) << 6);
    size_t o1 = (((size_t)(b * SEQ + qrow1) * NH + h) << 6);
#pragma unroll
    for (int nt = 0; nt < 8; nt++) {
        int dim = nt * 8 + (lane & 3) * 2;
        uint32_t hp, lp;
        split_pair(oacc[nt][0] * inv0, oacc[nt][1] * inv0, hp, lp);
        *(uint32_t*)(g_oh + o0 + dim) = hp;
        *(uint32_t*)(g_ol + o0 + dim) = lp;
        split_pair(oacc[nt][2] * inv1, oacc[nt][3] * inv1, hp, lp);
        *(uint32_t*)(g_oh + o1 + dim) = hp;
        *(uint32_t*)(g_ol + o1 + dim) = lp;
    }
}

// ---------------- launch ---------------------------------------------------
extern "C" void kernel_launch(void* const* d_in, const int* in_sizes, int n_in,
                              void* d_out, int out_size)
{
    const float* x    = (const float*)d_in[0];
    const float* cosp = (const float*)d_in[1];
    const float* sinp = (const float*)d_in[2];
    const float* Wq   = (const float*)d_in[3];
    const float* Wk   = (const float*)d_in[4];
    const float* Wv   = (const float*)d_in[5];
    const float* Wo   = (const float*)d_in[6];
    float* out = (float*)d_out;

    float *q, *k, *v;
    __half *xh, *xl, *wqth, *wqtl, *wkth, *wktl, *wvth, *wvtl, *woth, *wotl;
    __half *qh, *ql, *kh, *kl, *oh, *ol;
    cudaGetSymbolAddress((void**)&q, g_q);
    cudaGetSymbolAddress((void**)&k, g_k);
    cudaGetSymbolAddress((void**)&v, g_v);
    cudaGetSymbolAddress((void**)&xh, g_xh);
    cudaGetSymbolAddress((void**)&xl, g_xl);
    cudaGetSymbolAddress((void**)&wqth, g_wqth);
    cudaGetSymbolAddress((void**)&wqtl, g_wqtl);
    cudaGetSymbolAddress((void**)&wkth, g_wkth);
    cudaGetSymbolAddress((void**)&wktl, g_wktl);
    cudaGetSymbolAddress((void**)&wvth, g_wvth);
    cudaGetSymbolAddress((void**)&wvtl, g_wvtl);
    cudaGetSymbolAddress((void**)&woth, g_woth);
    cudaGetSymbolAddress((void**)&wotl, g_wotl);
    cudaGetSymbolAddress((void**)&qh, g_qh);
    cudaGetSymbolAddress((void**)&ql, g_ql);
    cudaGetSymbolAddress((void**)&kh, g_kh);
    cudaGetSymbolAddress((void**)&kl, g_kl);
    cudaGetSymbolAddress((void**)&oh, g_oh);
    cudaGetSymbolAddress((void**)&ol, g_ol);

    cudaFuncSetAttribute(gemm_mma_kernel,
                         cudaFuncAttributeMaxDynamicSharedMemorySize, GEMM_SMEM);
    cudaFuncSetAttribute(attn_mma_kernel,
                         cudaFuncAttributeMaxDynamicSharedMemorySize, ATTN_SMEM);

    dim3 tb(32, 8);
    split_kernel<<<(TOK * D_MODEL / 4 + 255) / 256, 256>>>(x, xh, xl, TOK * D_MODEL / 4);
    wsplit_t_kernel<<<dim3(D_MODEL / 32, D_MODEL / 32), tb>>>(Wq, wqth, wqtl, D_MODEL, D_MODEL);
    wsplit_t_kernel<<<dim3(KVD / 32, D_MODEL / 32), tb>>>(Wk, wkth, wktl, D_MODEL, KVD);
    wsplit_t_kernel<<<dim3(KVD / 32, D_MODEL / 32), tb>>>(Wv, wvth, wvtl, D_MODEL, KVD);
    wsplit_t_kernel<<<dim3(D_MODEL / 32, D_MODEL / 32), tb>>>(Wo, woth, wotl, D_MODEL, D_MODEL);

    gemm_mma_kernel<<<dim3(D_MODEL / GBN, TOK / GBM), 256, GEMM_SMEM>>>(
        xh, xl, wqth, wqtl, q, TOK, D_MODEL, D_MODEL);
    gemm_mma_kernel<<<dim3(KVD / GBN, TOK / GBM), 256, GEMM_SMEM>>>(
        xh, xl, wkth, wktl, k, TOK, KVD, D_MODEL);
    gemm_mma_kernel<<<dim3(KVD / GBN, TOK / GBM), 256, GEMM_SMEM>>>(
        xh, xl, wvth, wvtl, v, TOK, KVD, D_MODEL);

    rope_rms_split_kernel<<<(TOK * NH) / 8, 256>>>(q, qh, ql, cosp, sinp, NH);
    rope_rms_split_kernel<<<(TOK * NKV) / 8, 256>>>(k, kh, kl, cosp, sinp, NKV);
    vsplit_t_kernel<<<dim3(HD / 32, SEQ / 32, BATCH * NKV), tb>>>();

    attn_mma_kernel<<<dim3(SEQ / 128, NH, BATCH), 256, ATTN_SMEM>>>();

    gemm_mma_kernel<<<dim3(D_MODEL / GBN, TOK / GBM), 256, GEMM_SMEM>>>(
        oh, ol, woth, wotl, out, TOK, D_MODEL, D_MODEL);
}

// round 13
// speedup vs baseline: 1.4728x; 1.0139x over previous
#include <cuda_runtime.h>
#include <cuda_fp16.h>
#include <math.h>
#include <stdint.h>

#define D_MODEL 2048
#define NH 32
#define NKV 8
#define HD 64
#define BATCH 2
#define SEQ 2048
#define TOK (BATCH * SEQ)   // 4096
#define KVD (NKV * HD)      // 512

// ---------------- scratch (device globals; no allocation allowed) ----------
__device__ float  g_q[(size_t)TOK * NH * HD];
__device__ float  g_k[(size_t)TOK * NKV * HD];
__device__ float  g_v[(size_t)TOK * NKV * HD];
__device__ __half g_xh[(size_t)TOK * D_MODEL];
__device__ __half g_xl[(size_t)TOK * D_MODEL];
__device__ __half g_wqth[(size_t)D_MODEL * D_MODEL];
__device__ __half g_wqtl[(size_t)D_MODEL * D_MODEL];
__device__ __half g_wkvh[(size_t)(2 * KVD) * D_MODEL];   // Wk^T | Wv^T hi
__device__ __half g_wkvl[(size_t)(2 * KVD) * D_MODEL];   // lo
__device__ __half g_woth[(size_t)D_MODEL * D_MODEL];
__device__ __half g_wotl[(size_t)D_MODEL * D_MODEL];
__device__ __half g_qh[(size_t)TOK * NH * HD];
__device__ __half g_ql[(size_t)TOK * NH * HD];
__device__ __half g_kh[(size_t)TOK * NKV * HD];
__device__ __half g_kl[(size_t)TOK * NKV * HD];
__device__ __half g_vth[(size_t)BATCH * NKV * HD * SEQ];
__device__ __half g_vtl[(size_t)BATCH * NKV * HD * SEQ];
__device__ __half g_oh[(size_t)TOK * NH * HD];
__device__ __half g_ol[(size_t)TOK * NH * HD];

// ======================= helpers (portable PTX only) ========================
__device__ __forceinline__ uint32_t smem_u32(const void* p) {
    uint32_t a;
    asm("{ .reg .u64 t; cvta.to.shared.u64 t, %1; cvt.u32.u64 %0, t; }"
        : "=r"(a) : "l"(p));
    return a;
}
#define SWZ(o)   ((o) ^ (((o) >> 3) & 0x70))
#define SWZ64(o) ((o) ^ (((o) >> 3) & 0x30))

#define LDSM4(r, a) \
    asm volatile("ldmatrix.sync.aligned.m8n8.x4.shared.b16 {%0,%1,%2,%3}, [%4];" \
        : "=r"((r)[0]), "=r"((r)[1]), "=r"((r)[2]), "=r"((r)[3]) : "r"(a))

#define MMA_F16(c, a, b0, b1) \
    asm volatile("mma.sync.aligned.m16n8k16.row.col.f32.f16.f16.f32 " \
        "{%0,%1,%2,%3}, {%4,%5,%6,%7}, {%8,%9}, {%0,%1,%2,%3};" \
        : "+f"((c)[0]), "+f"((c)[1]), "+f"((c)[2]), "+f"((c)[3]) \
        : "r"((a)[0]), "r"((a)[1]), "r"((a)[2]), "r"((a)[3]), \
          "r"(b0), "r"(b1))

#define CP16(dst, src) \
    asm volatile("cp.async.ca.shared.global [%0], [%1], 16;" \
                 :: "r"(dst), "l"(src) : "memory")
#define CP_COMMIT() asm volatile("cp.async.commit_group;" ::: "memory")
#define CP_WAIT0()  asm volatile("cp.async.wait_group 0;" ::: "memory")

__device__ __forceinline__ uint32_t packh2(__half a, __half b) {
    __half2 t = __halves2half2(a, b);
    return *(uint32_t*)&t;
}
__device__ __forceinline__ void split_pair(float f0, float f1,
                                           uint32_t& hp, uint32_t& lp) {
    __half h0 = __float2half_rn(f0), h1 = __float2half_rn(f1);
    __half l0 = __float2half_rn(f0 - __half2float(h0));
    __half l1 = __float2half_rn(f1 - __half2float(h1));
    hp = packh2(h0, h1); lp = packh2(l0, l1);
}

// ---------------- elementwise split: fp32 -> hi/lo fp16 planes -------------
__global__ void split_kernel(const float* __restrict__ in,
                             __half* __restrict__ hi, __half* __restrict__ lo,
                             int n4)
{
    int i = blockIdx.x * blockDim.x + threadIdx.x;
    if (i >= n4) return;
    float4 v = ((const float4*)in)[i];
    uint32_t h01, l01, h23, l23;
    split_pair(v.x, v.y, h01, l01);
    split_pair(v.z, v.w, h23, l23);
    ((uint2*)hi)[i] = make_uint2(h01, h23);
    ((uint2*)lo)[i] = make_uint2(l01, l23);
}

// ---- transpose + split: W[K,C] fp32 -> rows [rowoff..rowoff+C) of planes --
__global__ void wsplit_t_kernel(const float* __restrict__ in,
                                __half* __restrict__ hi, __half* __restrict__ lo,
                                int R, int C, int rowoff)
{
    __shared__ float t[32][33];
    const int bx = blockIdx.x * 32, by = blockIdx.y * 32;
    const int tx = threadIdx.x, ty = threadIdx.y;
#pragma unroll
    for (int j = 0; j < 32; j += 8)
        t[ty + j][tx] = in[(size_t)(by + ty + j) * C + bx + tx];
    __syncthreads();
#pragma unroll
    for (int j = 0; j < 32; j += 8) {
        float f = t[tx][ty + j];
        __half h = __float2half_rn(f);
        size_t o = (size_t)(rowoff + bx + ty + j) * R + by + tx;
        hi[o] = h;
        lo[o] = __float2half_rn(f - __half2float(h));
    }
}

// ---------------- V: split + transpose -> Vt[b][kvh][dim][seq] -------------
__global__ void vsplit_t_kernel()
{
    __shared__ float t[32][33];
    const int bkv = blockIdx.z;
    const int b = bkv >> 3, kvh = bkv & 7;
    const int s0 = blockIdx.y * 32;
    const int d0 = blockIdx.x * 32;
    const int tx = threadIdx.x, ty = threadIdx.y;
#pragma unroll
    for (int j = 0; j < 32; j += 8)
        t[ty + j][tx] = g_v[(((size_t)(b * SEQ + s0 + ty + j) * NKV + kvh) << 6) + d0 + tx];
    __syncthreads();
#pragma unroll
    for (int j = 0; j < 32; j += 8) {
        float f = t[tx][ty + j];
        __half h = __float2half_rn(f);
        size_t o = ((size_t)(bkv * HD) + d0 + ty + j) * SEQ + s0 + tx;
        g_vth[o] = h;
        g_vtl[o] = __float2half_rn(f - __half2float(h));
    }
}

// ---------------- RoPE + RMSNorm, writes hi/lo fp16 planes -----------------
__global__ void rope_rms_split_kernel(const float* __restrict__ src,
                                      __half* __restrict__ hi, __half* __restrict__ lo,
                                      const float* __restrict__ cosp,
                                      const float* __restrict__ sinp,
                                      int nheads)
{
    int gw = (blockIdx.x * blockDim.x + threadIdx.x) >> 5;
    int lane = threadIdx.x & 31;
    int total = TOK * nheads;
    if (gw >= total) return;
    int tok = gw / nheads;
    int l = tok % SEQ;

    const float* p = src + (size_t)gw * HD;
    float x1 = p[lane];
    float x2 = p[lane + 32];
    float c = cosp[l * 32 + lane];
    float s = sinp[l * 32 + lane];
    float o1 = x1 * c - x2 * s;
    float o2 = x2 * c + x1 * s;
    float ss = o1 * o1 + o2 * o2;
#pragma unroll
    for (int off = 16; off > 0; off >>= 1)
        ss += __shfl_xor_sync(0xffffffffu, ss, off);
    float r = rsqrtf(ss * (1.0f / 64.0f) + 1e-6f);
    o1 *= r; o2 *= r;
    __half h1 = __float2half_rn(o1), h2 = __float2half_rn(o2);
    hi[(size_t)gw * HD + lane] = h1;
    hi[(size_t)gw * HD + lane + 32] = h2;
    lo[(size_t)gw * HD + lane] = __float2half_rn(o1 - __half2float(h1));
    lo[(size_t)gw * HD + lane + 32] = __float2half_rn(o2 - __half2float(h2));
}

// ======================= 3xFP16 GEMM, cp.async pipeline (R9) ===============
// Templated epilogue target: if Csplit != nullptr and col >= KVD, write there.
#define GBM 128
#define GBN 128
#define GBK 32
#define APL 8192
#define OFF_AHI 0
#define OFF_ALO (APL)
#define OFF_BHI (2 * APL)
#define OFF_BLO (3 * APL)
#define BUFSZ (4 * APL)                // 32 KB / stage
#define GEMM_SMEM (2 * BUFSZ)          // 64 KB

__device__ __forceinline__ void gemm_body(
    const __half* Ah, const __half* Al,
    const __half* Bh, const __half* Bl,
    float* Cout, int Nout,       // output buffer (already offset for this tile)
    int n0, int m0, int K)
{
    extern __shared__ char sm[];
    const uint32_t sb = smem_u32(sm);
    const int tid = threadIdx.x;
    const int wid = tid >> 5, lane = tid & 31;
    const int wm = wid & 3;
    const int wn = wid >> 2;

    const __half* srcs[8];
    uint32_t dsts[8];
#pragma unroll
    for (int i = 0; i < 8; i++) {
        int gidx = tid + i * 256;
        int plane = gidx >> 9;
        int c = gidx & 511;
        int r = c >> 2, q = c & 3;
        const __half* base = (plane == 0) ? Ah : (plane == 1) ? Al
                           : (plane == 2) ? Bh : Bl;
        int row = (plane < 2 ? m0 : n0) + r;
        srcs[i] = base + (size_t)row * K + q * 8;
        dsts[i] = (uint32_t)(plane * APL) + SWZ64((uint32_t)(r * 64 + q * 16));
    }

    const int arowl = lane & 15;
    const int ca = lane >> 4;
    uint32_t a_rb[2]; int a_rx[2];
#pragma unroll
    for (int mi = 0; mi < 2; mi++) {
        int r = wm * 32 + mi * 16 + arowl;
        a_rb[mi] = (uint32_t)(r * 64); a_rx[mi] = (r >> 1) & 3;
    }
    const int lrowb = (lane & 7) + ((lane >> 4) << 3);
    const int cb = (lane >> 3) & 1;
    uint32_t b_rb[4]; int b_rx[4];
#pragma unroll
    for (int bi = 0; bi < 4; bi++) {
        int r = wn * 64 + bi * 16 + lrowb;
        b_rb[bi] = (uint32_t)(r * 64); b_rx[bi] = (r >> 1) & 3;
    }

    float acc[2][8][4];
#pragma unroll
    for (int mi = 0; mi < 2; mi++)
#pragma unroll
        for (int ni = 0; ni < 8; ni++)
#pragma unroll
            for (int j = 0; j < 4; j++) acc[mi][ni][j] = 0.0f;

#pragma unroll
    for (int i = 0; i < 8; i++) CP16(sb + dsts[i], srcs[i]);
    CP_COMMIT();
    CP_WAIT0();
    __syncthreads();

    const int S = K / GBK;
    for (int s = 0; s < S; s++) {
        const uint32_t base = sb + (uint32_t)(s & 1) * BUFSZ;

        if (s + 1 < S) {
            const uint32_t nb = (uint32_t)((s + 1) & 1) * BUFSZ;
            const int k0 = (s + 1) * GBK;
#pragma unroll
            for (int i = 0; i < 8; i++) CP16(sb + nb + dsts[i], srcs[i] + k0);
            CP_COMMIT();
        }

#pragma unroll
        for (int ks = 0; ks < 2; ks++) {
            uint32_t ah[2][4], al[2][4];
#pragma unroll
            for (int mi = 0; mi < 2; mi++) {
                uint32_t off = a_rb[mi] + (uint32_t)((((ks * 2 + ca) ^ a_rx[mi])) << 4);
                LDSM4(ah[mi], base + OFF_AHI + off);
                LDSM4(al[mi], base + OFF_ALO + off);
            }
#pragma unroll
            for (int nt = 0; nt < 4; nt++) {
                uint32_t bh[4], bl[4];
                uint32_t off = b_rb[nt] + (uint32_t)((((ks * 2 + cb) ^ b_rx[nt])) << 4);
                LDSM4(bh, base + OFF_BHI + off);
                LDSM4(bl, base + OFF_BLO + off);
#pragma unroll
                for (int j = 0; j < 2; j++) {
                    int ni = nt * 2 + j;
#pragma unroll
                    for (int mi = 0; mi < 2; mi++) {
                        MMA_F16(acc[mi][ni], ah[mi], bh[j * 2], bh[j * 2 + 1]);
                        MMA_F16(acc[mi][ni], ah[mi], bl[j * 2], bl[j * 2 + 1]);
                        MMA_F16(acc[mi][ni], al[mi], bh[j * 2], bh[j * 2 + 1]);
                    }
                }
            }
        }

        if (s + 1 < S) {
            CP_WAIT0();
            __syncthreads();
        }
    }

#pragma unroll
    for (int mi = 0; mi < 2; mi++)
#pragma unroll
        for (int ni = 0; ni < 8; ni++) {
            int row = m0 + wm * 32 + mi * 16 + (lane >> 2);
            int col = wn * 64 + ni * 8 + (lane & 3) * 2;
            *(float2*)(Cout + (size_t)row * Nout + col) =
                make_float2(acc[mi][ni][0], acc[mi][ni][1]);
            *(float2*)(Cout + (size_t)(row + 8) * Nout + col) =
                make_float2(acc[mi][ni][2], acc[mi][ni][3]);
        }
}

__global__ __launch_bounds__(256, 2)
void gemm_mma_kernel(const __half* __restrict__ Ah, const __half* __restrict__ Al,
                     const __half* __restrict__ Bh, const __half* __restrict__ Bl,
                     float* __restrict__ C, int M, int N, int K)
{
    const int m0 = blockIdx.y * GBM;
    const int n0 = blockIdx.x * GBN;
    gemm_body(Ah, Al, Bh, Bl, C + n0, N, n0, m0, K);
}

// fused K|V projection: B rows [0,512)=Wk^T, [512,1024)=Wv^T; outputs split.
__global__ __launch_bounds__(256, 2)
void gemm_mma_kv_kernel(const __half* __restrict__ Ah, const __half* __restrict__ Al,
                        const __half* __restrict__ Bh, const __half* __restrict__ Bl,
                        float* __restrict__ Ck, float* __restrict__ Cv, int K)
{
    const int m0 = blockIdx.y * GBM;
    const int n0 = blockIdx.x * GBN;          // 0..896, never straddles 512
    float* Cout = (n0 < KVD) ? (Ck + n0) : (Cv + (n0 - KVD));
    gemm_body(Ah, Al, Bh, Bl, Cout, KVD, n0, m0, K);
}

// =============== Flash attention: R9 (serial K/V load, P in registers) =====
#define QHI_B 0u
#define QLO_B 16384u
#define KHI_B 32768u
#define VHI_B 49152u        // KHI 32768, KLO 40960, VHI 49152, VLO 57344
#define ATTN_SMEM 65536     // 64 KB -> 2 CTAs/SM

__global__ __launch_bounds__(256, 2) void attn_mma_kernel()
{
    extern __shared__ float smf[];
    const uint32_t sb = smem_u32(smf);
    const int qt = (int)gridDim.x - 1 - (int)blockIdx.x;
    const int h = blockIdx.y, b = blockIdx.z;
    const int kvh = h >> 2;
    const int tid = threadIdx.x;
    const int warp = tid >> 5, lane = tid & 31;
    const int q0 = qt * 128;

#pragma unroll
    for (int i = 0; i < 8; i++) {
        int gidx = tid + i * 256;
        int plane = gidx >> 10;
        int c = gidx & 1023;
        int r = c >> 3, q = c & 7;
        const __half* src = (plane ? g_ql : g_qh)
            + (((size_t)(b * SEQ + q0 + r) * NH + h) << 6) + q * 8;
        CP16(sb + QHI_B + (uint32_t)plane * 16384u + SWZ((uint32_t)(r * 128 + q * 16)), src);
    }
    CP_COMMIT();

    const __half* kv_src[8];
    uint32_t kv_dst[8];
    int kv_step[8];
#pragma unroll
    for (int i = 0; i < 8; i++) {
        int gidx = tid + i * 256;
        int plane = gidx >> 9;
        int c = gidx & 511;
        int r = c >> 3, q = c & 7;
        if (plane < 2) {
            kv_src[i] = (plane ? g_kl : g_kh)
                + (((size_t)(b * SEQ + r) * NKV + kvh) << 6) + q * 8;
            kv_step[i] = NKV * HD;
        } else {
            kv_src[i] = ((plane == 3) ? g_vtl : g_vth)
                + ((size_t)((b * NKV + kvh) * HD) + r) * SEQ + q * 8;
            kv_step[i] = 1;
        }
        kv_dst[i] = KHI_B + (uint32_t)plane * 8192u + SWZ((uint32_t)(r * 128 + q * 16));
    }

    const int arowl = lane & 15;
    const int ca = lane >> 4;
    const int lrowb = (lane & 7) + ((lane >> 4) << 3);
    const int cb = (lane >> 3) & 1;
    const int ar = warp * 16 + arowl;
    const uint32_t a_rb = (uint32_t)(ar * 128);
    const int a_rx = ar & 7;
    uint32_t b_rb[4]; int b_rx[4];
#pragma unroll
    for (int bi = 0; bi < 4; bi++) {
        int r = bi * 16 + lrowb;
        b_rb[bi] = (uint32_t)(r * 128); b_rx[bi] = r & 7;
    }

    float m0 = -1e30f, m1 = -1e30f, l0 = 0.f, l1 = 0.f;
    float oacc[8][4];
#pragma unroll
    for (int nt = 0; nt < 8; nt++)
#pragma unroll
        for (int j = 0; j < 4; j++) oacc[nt][j] = 0.f;

    const int rloc = lane >> 2;
    const int qrow0 = q0 + warp * 16 + rloc;
    const int qrow1 = qrow0 + 8;
    const int ktmax = 2 * qt + 1;

    for (int kt = 0; kt <= ktmax; kt++) {
        const int k0 = kt * 64;
        __syncthreads();
#pragma unroll
        for (int i = 0; i < 8; i++)
            CP16(sb + kv_dst[i], kv_src[i] + (size_t)k0 * kv_step[i]);
        CP_COMMIT();
        CP_WAIT0();
        __syncthreads();

        float sacc[8][4];
#pragma unroll
        for (int nt = 0; nt < 8; nt++)
#pragma unroll
            for (int j = 0; j < 4; j++) sacc[nt][j] = 0.f;

#pragma unroll
        for (int ks = 0; ks < 4; ks++) {
            uint32_t qh[4], ql[4];
            uint32_t aoff = a_rb + (uint32_t)((((ks * 2 + ca) ^ a_rx)) << 4);
            LDSM4(qh, sb + QHI_B + aoff);
            LDSM4(ql, sb + QLO_B + aoff);
#pragma unroll
            for (int nt = 0; nt < 4; nt++) {
                uint32_t kh[4], kl[4];
                uint32_t boff = b_rb[nt] + (uint32_t)((((ks * 2 + cb) ^ b_rx[nt])) << 4);
                LDSM4(kh, sb + KHI_B + boff);
                LDSM4(kl, sb + KHI_B + 8192u + boff);
#pragma unroll
                for (int j = 0; j < 2; j++) {
                    int ni = nt * 2 + j;
                    MMA_F16(sacc[ni], qh, kh[j * 2], kh[j * 2 + 1]);
                    MMA_F16(sacc[ni], qh, kl[j * 2], kl[j * 2 + 1]);
                    MMA_F16(sacc[ni], ql, kh[j * 2], kh[j * 2 + 1]);
                }
            }
        }

        const bool domask = (k0 + 63 > q0);
#pragma unroll
        for (int nt = 0; nt < 8; nt++) {
            int keyb = k0 + nt * 8 + (lane & 3) * 2;
#pragma unroll
            for (int j = 0; j < 4; j++) {
                float s = sacc[nt][j] * 0.125f;
                if (domask) {
                    int key = keyb + (j & 1);
                    int qq = (j < 2) ? qrow0 : qrow1;
                    if (key > qq) s = -1e30f;
                }
                sacc[nt][j] = s;
            }
        }
        float mx0 = -1e30f, mx1 = -1e30f;
#pragma unroll
        for (int nt = 0; nt < 8; nt++) {
            mx0 = fmaxf(mx0, fmaxf(sacc[nt][0], sacc[nt][1]));
            mx1 = fmaxf(mx1, fmaxf(sacc[nt][2], sacc[nt][3]));
        }
        mx0 = fmaxf(mx0, __shfl_xor_sync(0xffffffffu, mx0, 1));
        mx0 = fmaxf(mx0, __shfl_xor_sync(0xffffffffu, mx0, 2));
        mx1 = fmaxf(mx1, __shfl_xor_sync(0xffffffffu, mx1, 1));
        mx1 = fmaxf(mx1, __shfl_xor_sync(0xffffffffu, mx1, 2));
        float nm0 = fmaxf(m0, mx0), nm1 = fmaxf(m1, mx1);
        float c0 = __expf(m0 - nm0), c1 = __expf(m1 - nm1);
        m0 = nm0; m1 = nm1;
        float rs0 = 0.f, rs1 = 0.f;
#pragma unroll
        for (int nt = 0; nt < 8; nt++) {
            float p0 = __expf(sacc[nt][0] - nm0);
            float p1 = __expf(sacc[nt][1] - nm0);
            float p2 = __expf(sacc[nt][2] - nm1);
            float p3 = __expf(sacc[nt][3] - nm1);
            sacc[nt][0] = p0; sacc[nt][1] = p1; sacc[nt][2] = p2; sacc[nt][3] = p3;
            rs0 += p0 + p1; rs1 += p2 + p3;
        }
        rs0 += __shfl_xor_sync(0xffffffffu, rs0, 1);
        rs0 += __shfl_xor_sync(0xffffffffu, rs0, 2);
        rs1 += __shfl_xor_sync(0xffffffffu, rs1, 1);
        rs1 += __shfl_xor_sync(0xffffffffu, rs1, 2);
        l0 = l0 * c0 + rs0;
        l1 = l1 * c1 + rs1;
#pragma unroll
        for (int nt = 0; nt < 8; nt++) {
            oacc[nt][0] *= c0; oacc[nt][1] *= c0;
            oacc[nt][2] *= c1; oacc[nt][3] *= c1;
        }

#pragma unroll
        for (int ks = 0; ks < 4; ks++) {
            uint32_t pa[4], pb[4];
            split_pair(sacc[2 * ks][0],     sacc[2 * ks][1],     pa[0], pb[0]);
            split_pair(sacc[2 * ks][2],     sacc[2 * ks][3],     pa[1], pb[1]);
            split_pair(sacc[2 * ks + 1][0], sacc[2 * ks + 1][1], pa[2], pb[2]);
            split_pair(sacc[2 * ks + 1][2], sacc[2 * ks + 1][3], pa[3], pb[3]);
#pragma unroll
            for (int nt = 0; nt < 4; nt++) {
                uint32_t vh[4], vl[4];
                uint32_t boff = b_rb[nt] + (uint32_t)((((ks * 2 + cb) ^ b_rx[nt])) << 4);
                LDSM4(vh, sb + VHI_B + boff);
                LDSM4(vl, sb + VHI_B + 8192u + boff);
#pragma unroll
                for (int j = 0; j < 2; j++) {
                    int ni = nt * 2 + j;
                    MMA_F16(oacc[ni], pa, vh[j * 2], vh[j * 2 + 1]);
                    MMA_F16(oacc[ni], pa, vl[j * 2], vl[j * 2 + 1]);
                    MMA_F16(oacc[ni], pb, vh[j * 2], vh[j * 2 + 1]);
                }
            }
        }
    }

    float inv0 = 1.0f / l0, inv1 = 1.0f / l1;
    size_t o0 = (((size_t)(b * SEQ + qrow0) * NH + h) << 6);
    size_t o1 = (((size_t)(b * SEQ + qrow1) * NH + h) << 6);
#pragma unroll
    for (int nt = 0; nt < 8; nt++) {
        int dim = nt * 8 + (lane & 3) * 2;
        uint32_t hp, lp;
        split_pair(oacc[nt][0] * inv0, oacc[nt][1] * inv0, hp, lp);
        *(uint32_t*)(g_oh + o0 + dim) = hp;
        *(uint32_t*)(g_ol + o0 + dim) = lp;
        split_pair(oacc[nt][2] * inv1, oacc[nt][3] * inv1, hp, lp);
        *(uint32_t*)(g_oh + o1 + dim) = hp;
        *(uint32_t*)(g_ol + o1 + dim) = lp;
    }
}

// ---------------- launch ---------------------------------------------------
extern "C" void kernel_launch(void* const* d_in, const int* in_sizes, int n_in,
                              void* d_out, int out_size)
{
    const float* x    = (const float*)d_in[0];
    const float* cosp = (const float*)d_in[1];
    const float* sinp = (const float*)d_in[2];
    const float* Wq   = (const float*)d_in[3];
    const float* Wk   = (const float*)d_in[4];
    const float* Wv   = (const float*)d_in[5];
    const float* Wo   = (const float*)d_in[6];
    float* out = (float*)d_out;

    float *q, *k, *v;
    __half *xh, *xl, *wqth, *wqtl, *wkvh, *wkvl, *woth, *wotl;
    __half *qh, *ql, *kh, *kl, *oh, *ol;
    cudaGetSymbolAddress((void**)&q, g_q);
    cudaGetSymbolAddress((void**)&k, g_k);
    cudaGetSymbolAddress((void**)&v, g_v);
    cudaGetSymbolAddress((void**)&xh, g_xh);
    cudaGetSymbolAddress((void**)&xl, g_xl);
    cudaGetSymbolAddress((void**)&wqth, g_wqth);
    cudaGetSymbolAddress((void**)&wqtl, g_wqtl);
    cudaGetSymbolAddress((void**)&wkvh, g_wkvh);
    cudaGetSymbolAddress((void**)&wkvl, g_wkvl);
    cudaGetSymbolAddress((void**)&woth, g_woth);
    cudaGetSymbolAddress((void**)&wotl, g_wotl);
    cudaGetSymbolAddress((void**)&qh, g_qh);
    cudaGetSymbolAddress((void**)&ql, g_ql);
    cudaGetSymbolAddress((void**)&kh, g_kh);
    cudaGetSymbolAddress((void**)&kl, g_kl);
    cudaGetSymbolAddress((void**)&oh, g_oh);
    cudaGetSymbolAddress((void**)&ol, g_ol);

    cudaFuncSetAttribute(gemm_mma_kernel,
                         cudaFuncAttributeMaxDynamicSharedMemorySize, GEMM_SMEM);
    cudaFuncSetAttribute(gemm_mma_kv_kernel,
                         cudaFuncAttributeMaxDynamicSharedMemorySize, GEMM_SMEM);
    cudaFuncSetAttribute(attn_mma_kernel,
                         cudaFuncAttributeMaxDynamicSharedMemorySize, ATTN_SMEM);

    dim3 tb(32, 8);
    split_kernel<<<(TOK * D_MODEL / 4 + 255) / 256, 256>>>(x, xh, xl, TOK * D_MODEL / 4);
    wsplit_t_kernel<<<dim3(D_MODEL / 32, D_MODEL / 32), tb>>>(Wq, wqth, wqtl, D_MODEL, D_MODEL, 0);
    wsplit_t_kernel<<<dim3(KVD / 32, D_MODEL / 32), tb>>>(Wk, wkvh, wkvl, D_MODEL, KVD, 0);
    wsplit_t_kernel<<<dim3(KVD / 32, D_MODEL / 32), tb>>>(Wv, wkvh, wkvl, D_MODEL, KVD, KVD);
    wsplit_t_kernel<<<dim3(D_MODEL / 32, D_MODEL / 32), tb>>>(Wo, woth, wotl, D_MODEL, D_MODEL, 0);

    // Q projection (unchanged) + fused K|V projection (one wave)
    gemm_mma_kernel<<<dim3(D_MODEL / GBN, TOK / GBM), 256, GEMM_SMEM>>>(
        xh, xl, wqth, wqtl, q, TOK, D_MODEL, D_MODEL);
    gemm_mma_kv_kernel<<<dim3((2 * KVD) / GBN, TOK / GBM), 256, GEMM_SMEM>>>(
        xh, xl, wkvh, wkvl, k, v, D_MODEL);

    rope_rms_split_kernel<<<(TOK * NH) / 8, 256>>>(q, qh, ql, cosp, sinp, NH);
    rope_rms_split_kernel<<<(TOK * NKV) / 8, 256>>>(k, kh, kl, cosp, sinp, NKV);
    vsplit_t_kernel<<<dim3(HD / 32, SEQ / 32, BATCH * NKV), tb>>>();

    attn_mma_kernel<<<dim3(SEQ / 128, NH, BATCH), 256, ATTN_SMEM>>>();

    gemm_mma_kernel<<<dim3(D_MODEL / GBN, TOK / GBM), 256, GEMM_SMEM>>>(
        oh, ol, woth, wotl, out, TOK, D_MODEL, D_MODEL);
}

// round 14
// speedup vs baseline: 1.5047x; 1.0217x over previous
#include <cuda_runtime.h>
#include <cuda_fp16.h>
#include <math.h>
#include <stdint.h>

#define D_MODEL 2048
#define NH 32
#define NKV 8
#define HD 64
#define BATCH 2
#define SEQ 2048
#define TOK (BATCH * SEQ)   // 4096
#define KVD (NKV * HD)      // 512

// ---------------- scratch (device globals; no allocation allowed) ----------
__device__ float  g_v[(size_t)TOK * NKV * HD];
__device__ __half g_xh[(size_t)TOK * D_MODEL];
__device__ __half g_xl[(size_t)TOK * D_MODEL];
__device__ __half g_wqth[(size_t)D_MODEL * D_MODEL];
__device__ __half g_wqtl[(size_t)D_MODEL * D_MODEL];
__device__ __half g_wkvh[(size_t)(2 * KVD) * D_MODEL];   // Wk^T | Wv^T hi
__device__ __half g_wkvl[(size_t)(2 * KVD) * D_MODEL];   // lo
__device__ __half g_woth[(size_t)D_MODEL * D_MODEL];
__device__ __half g_wotl[(size_t)D_MODEL * D_MODEL];
__device__ __half g_qh[(size_t)TOK * NH * HD];
__device__ __half g_ql[(size_t)TOK * NH * HD];
__device__ __half g_kh[(size_t)TOK * NKV * HD];
__device__ __half g_kl[(size_t)TOK * NKV * HD];
__device__ __half g_vth[(size_t)BATCH * NKV * HD * SEQ];
__device__ __half g_vtl[(size_t)BATCH * NKV * HD * SEQ];
__device__ __half g_oh[(size_t)TOK * NH * HD];
__device__ __half g_ol[(size_t)TOK * NH * HD];

// ======================= helpers (portable PTX only) ========================
__device__ __forceinline__ uint32_t smem_u32(const void* p) {
    uint32_t a;
    asm("{ .reg .u64 t; cvta.to.shared.u64 t, %1; cvt.u32.u64 %0, t; }"
        : "=r"(a) : "l"(p));
    return a;
}
#define SWZ(o)   ((o) ^ (((o) >> 3) & 0x70))
#define SWZ64(o) ((o) ^ (((o) >> 3) & 0x30))

#define LDSM4(r, a) \
    asm volatile("ldmatrix.sync.aligned.m8n8.x4.shared.b16 {%0,%1,%2,%3}, [%4];" \
        : "=r"((r)[0]), "=r"((r)[1]), "=r"((r)[2]), "=r"((r)[3]) : "r"(a))

#define MMA_F16(c, a, b0, b1) \
    asm volatile("mma.sync.aligned.m16n8k16.row.col.f32.f16.f16.f32 " \
        "{%0,%1,%2,%3}, {%4,%5,%6,%7}, {%8,%9}, {%0,%1,%2,%3};" \
        : "+f"((c)[0]), "+f"((c)[1]), "+f"((c)[2]), "+f"((c)[3]) \
        : "r"((a)[0]), "r"((a)[1]), "r"((a)[2]), "r"((a)[3]), \
          "r"(b0), "r"(b1))

#define CP16(dst, src) \
    asm volatile("cp.async.ca.shared.global [%0], [%1], 16;" \
                 :: "r"(dst), "l"(src) : "memory")
#define CP_COMMIT() asm volatile("cp.async.commit_group;" ::: "memory")
#define CP_WAIT0()  asm volatile("cp.async.wait_group 0;" ::: "memory")

__device__ __forceinline__ uint32_t packh2(__half a, __half b) {
    __half2 t = __halves2half2(a, b);
    return *(uint32_t*)&t;
}
__device__ __forceinline__ void split_pair(float f0, float f1,
                                           uint32_t& hp, uint32_t& lp) {
    __half h0 = __float2half_rn(f0), h1 = __float2half_rn(f1);
    __half l0 = __float2half_rn(f0 - __half2float(h0));
    __half l1 = __float2half_rn(f1 - __half2float(h1));
    hp = packh2(h0, h1); lp = packh2(l0, l1);
}

// ---------------- elementwise split: fp32 -> hi/lo fp16 planes -------------
__global__ void split_kernel(const float* __restrict__ in,
                             __half* __restrict__ hi, __half* __restrict__ lo,
                             int n4)
{
    int i = blockIdx.x * blockDim.x + threadIdx.x;
    if (i >= n4) return;
    float4 v = ((const float4*)in)[i];
    uint32_t h01, l01, h23, l23;
    split_pair(v.x, v.y, h01, l01);
    split_pair(v.z, v.w, h23, l23);
    ((uint2*)hi)[i] = make_uint2(h01, h23);
    ((uint2*)lo)[i] = make_uint2(l01, l23);
}

// ---- transpose + split: W[K,C] fp32 -> rows [rowoff..rowoff+C) of planes --
__global__ void wsplit_t_kernel(const float* __restrict__ in,
                                __half* __restrict__ hi, __half* __restrict__ lo,
                                int R, int C, int rowoff)
{
    __shared__ float t[32][33];
    const int bx = blockIdx.x * 32, by = blockIdx.y * 32;
    const int tx = threadIdx.x, ty = threadIdx.y;
#pragma unroll
    for (int j = 0; j < 32; j += 8)
        t[ty + j][tx] = in[(size_t)(by + ty + j) * C + bx + tx];
    __syncthreads();
#pragma unroll
    for (int j = 0; j < 32; j += 8) {
        float f = t[tx][ty + j];
        __half h = __float2half_rn(f);
        size_t o = (size_t)(rowoff + bx + ty + j) * R + by + tx;
        hi[o] = h;
        lo[o] = __float2half_rn(f - __half2float(h));
    }
}

// ---------------- V: split + transpose -> Vt[b][kvh][dim][seq] -------------
__global__ void vsplit_t_kernel()
{
    __shared__ float t[32][33];
    const int bkv = blockIdx.z;
    const int b = bkv >> 3, kvh = bkv & 7;
    const int s0 = blockIdx.y * 32;
    const int d0 = blockIdx.x * 32;
    const int tx = threadIdx.x, ty = threadIdx.y;
#pragma unroll
    for (int j = 0; j < 32; j += 8)
        t[ty + j][tx] = g_v[(((size_t)(b * SEQ + s0 + ty + j) * NKV + kvh) << 6) + d0 + tx];
    __syncthreads();
#pragma unroll
    for (int j = 0; j < 32; j += 8) {
        float f = t[tx][ty + j];
        __half h = __float2half_rn(f);
        size_t o = ((size_t)(bkv * HD) + d0 + ty + j) * SEQ + s0 + tx;
        g_vth[o] = h;
        g_vtl[o] = __float2half_rn(f - __half2float(h));
    }
}

// ======================= 3xFP16 GEMM mainloop (R9/R13) ======================
#define GBM 128
#define GBN 128
#define GBK 32
#define APL 8192
#define OFF_AHI 0
#define OFF_ALO (APL)
#define OFF_BHI (2 * APL)
#define OFF_BLO (3 * APL)
#define BUFSZ (4 * APL)                // 32 KB / stage
#define GEMM_SMEM (2 * BUFSZ)          // 64 KB

__device__ __forceinline__ void gemm_mainloop(
    const __half* Ah, const __half* Al,
    const __half* Bh, const __half* Bl,
    int n0, int m0, int K, float acc[2][8][4])
{
    extern __shared__ char sm[];
    const uint32_t sb = smem_u32(sm);
    const int tid = threadIdx.x;
    const int wid = tid >> 5, lane = tid & 31;
    const int wm = wid & 3;
    const int wn = wid >> 2;

    const __half* srcs[8];
    uint32_t dsts[8];
#pragma unroll
    for (int i = 0; i < 8; i++) {
        int gidx = tid + i * 256;
        int plane = gidx >> 9;
        int c = gidx & 511;
        int r = c >> 2, q = c & 3;
        const __half* base = (plane == 0) ? Ah : (plane == 1) ? Al
                           : (plane == 2) ? Bh : Bl;
        int row = (plane < 2 ? m0 : n0) + r;
        srcs[i] = base + (size_t)row * K + q * 8;
        dsts[i] = (uint32_t)(plane * APL) + SWZ64((uint32_t)(r * 64 + q * 16));
    }

    const int arowl = lane & 15;
    const int ca = lane >> 4;
    uint32_t a_rb[2]; int a_rx[2];
#pragma unroll
    for (int mi = 0; mi < 2; mi++) {
        int r = wm * 32 + mi * 16 + arowl;
        a_rb[mi] = (uint32_t)(r * 64); a_rx[mi] = (r >> 1) & 3;
    }
    const int lrowb = (lane & 7) + ((lane >> 4) << 3);
    const int cb = (lane >> 3) & 1;
    uint32_t b_rb[4]; int b_rx[4];
#pragma unroll
    for (int bi = 0; bi < 4; bi++) {
        int r = wn * 64 + bi * 16 + lrowb;
        b_rb[bi] = (uint32_t)(r * 64); b_rx[bi] = (r >> 1) & 3;
    }

#pragma unroll
    for (int mi = 0; mi < 2; mi++)
#pragma unroll
        for (int ni = 0; ni < 8; ni++)
#pragma unroll
            for (int j = 0; j < 4; j++) acc[mi][ni][j] = 0.0f;

#pragma unroll
    for (int i = 0; i < 8; i++) CP16(sb + dsts[i], srcs[i]);
    CP_COMMIT();
    CP_WAIT0();
    __syncthreads();

    const int S = K / GBK;
    for (int s = 0; s < S; s++) {
        const uint32_t base = sb + (uint32_t)(s & 1) * BUFSZ;

        if (s + 1 < S) {
            const uint32_t nb = (uint32_t)((s + 1) & 1) * BUFSZ;
            const int k0 = (s + 1) * GBK;
#pragma unroll
            for (int i = 0; i < 8; i++) CP16(sb + nb + dsts[i], srcs[i] + k0);
            CP_COMMIT();
        }

#pragma unroll
        for (int ks = 0; ks < 2; ks++) {
            uint32_t ah[2][4], al[2][4];
#pragma unroll
            for (int mi = 0; mi < 2; mi++) {
                uint32_t off = a_rb[mi] + (uint32_t)((((ks * 2 + ca) ^ a_rx[mi])) << 4);
                LDSM4(ah[mi], base + OFF_AHI + off);
                LDSM4(al[mi], base + OFF_ALO + off);
            }
#pragma unroll
            for (int nt = 0; nt < 4; nt++) {
                uint32_t bh[4], bl[4];
                uint32_t off = b_rb[nt] + (uint32_t)((((ks * 2 + cb) ^ b_rx[nt])) << 4);
                LDSM4(bh, base + OFF_BHI + off);
                LDSM4(bl, base + OFF_BLO + off);
#pragma unroll
                for (int j = 0; j < 2; j++) {
                    int ni = nt * 2 + j;
#pragma unroll
                    for (int mi = 0; mi < 2; mi++) {
                        MMA_F16(acc[mi][ni], ah[mi], bh[j * 2], bh[j * 2 + 1]);
                        MMA_F16(acc[mi][ni], ah[mi], bl[j * 2], bl[j * 2 + 1]);
                        MMA_F16(acc[mi][ni], al[mi], bh[j * 2], bh[j * 2 + 1]);
                    }
                }
            }
        }

        if (s + 1 < S) {
            CP_WAIT0();
            __syncthreads();
        }
    }
}

// fused RoPE + per-head RMSNorm + hi/lo split epilogue.
// Warp's 64-col tile == one head; thread holds dims d (ni 0..3) and d+32 (ni 4..7).
__device__ __forceinline__ void epilogue_rope(
    float acc[2][8][4], int m0, int head, int nheads,
    __half* __restrict__ hi, __half* __restrict__ lo,
    const float* __restrict__ cosp, const float* __restrict__ sinp)
{
    const int lane = threadIdx.x & 31;
    const int wm = (threadIdx.x >> 5) & 3;
#pragma unroll
    for (int mi = 0; mi < 2; mi++) {
#pragma unroll
        for (int rr = 0; rr < 2; rr++) {      // rr=0 -> regs {0,1}; rr=1 -> {2,3}
            int row = m0 + wm * 32 + mi * 16 + (lane >> 2) + rr * 8;
            int l = row & (SEQ - 1);
            float o1v[8], o2v[8];
            float ss = 0.f;
#pragma unroll
            for (int ni = 0; ni < 4; ni++) {
#pragma unroll
                for (int j = 0; j < 2; j++) {
                    int d = ni * 8 + (lane & 3) * 2 + j;
                    float x1 = acc[mi][ni][rr * 2 + j];
                    float x2 = acc[mi][ni + 4][rr * 2 + j];
                    float c = cosp[l * 32 + d];
                    float s = sinp[l * 32 + d];
                    float o1 = x1 * c - x2 * s;
                    float o2 = x2 * c + x1 * s;
                    o1v[ni * 2 + j] = o1;
                    o2v[ni * 2 + j] = o2;
                    ss += o1 * o1 + o2 * o2;
                }
            }
            ss += __shfl_xor_sync(0xffffffffu, ss, 1);
            ss += __shfl_xor_sync(0xffffffffu, ss, 2);
            float r = rsqrtf(ss * (1.0f / 64.0f) + 1e-6f);
            size_t base = ((size_t)row * nheads + head) * HD;
#pragma unroll
            for (int ni = 0; ni < 4; ni++) {
                int d = ni * 8 + (lane & 3) * 2;
                uint32_t hp, lp;
                split_pair(o1v[ni * 2] * r, o1v[ni * 2 + 1] * r, hp, lp);
                *(uint32_t*)(hi + base + d) = hp;
                *(uint32_t*)(lo + base + d) = lp;
                split_pair(o2v[ni * 2] * r, o2v[ni * 2 + 1] * r, hp, lp);
                *(uint32_t*)(hi + base + d + 32) = hp;
                *(uint32_t*)(lo + base + d + 32) = lp;
            }
        }
    }
}

// plain fp32 epilogue (used for V tiles and O projection)
__device__ __forceinline__ void epilogue_f32(
    float acc[2][8][4], int m0, float* Cout, int Nout)
{
    const int lane = threadIdx.x & 31;
    const int wid = threadIdx.x >> 5;
    const int wm = wid & 3, wn = wid >> 2;
#pragma unroll
    for (int mi = 0; mi < 2; mi++)
#pragma unroll
        for (int ni = 0; ni < 8; ni++) {
            int row = m0 + wm * 32 + mi * 16 + (lane >> 2);
            int col = wn * 64 + ni * 8 + (lane & 3) * 2;
            *(float2*)(Cout + (size_t)row * Nout + col) =
                make_float2(acc[mi][ni][0], acc[mi][ni][1]);
            *(float2*)(Cout + (size_t)(row + 8) * Nout + col) =
                make_float2(acc[mi][ni][2], acc[mi][ni][3]);
        }
}

// Q projection + fused RoPE/RMS/split
__global__ __launch_bounds__(256, 2)
void gemm_q_kernel(const __half* __restrict__ Ah, const __half* __restrict__ Al,
                   const __half* __restrict__ Bh, const __half* __restrict__ Bl,
                   const float* __restrict__ cosp, const float* __restrict__ sinp,
                   int K)
{
    const int m0 = blockIdx.y * GBM;
    const int n0 = blockIdx.x * GBN;
    float acc[2][8][4];
    gemm_mainloop(Ah, Al, Bh, Bl, n0, m0, K, acc);
    const int head = (n0 + ((threadIdx.x >> 5) >> 2) * 64) >> 6;
    epilogue_rope(acc, m0, head, NH, g_qh, g_ql, cosp, sinp);
}

// fused K|V projection: K tiles get RoPE/RMS/split; V tiles write fp32 g_v.
__global__ __launch_bounds__(256, 2)
void gemm_kv_kernel(const __half* __restrict__ Ah, const __half* __restrict__ Al,
                    const __half* __restrict__ Bh, const __half* __restrict__ Bl,
                    const float* __restrict__ cosp, const float* __restrict__ sinp,
                    float* __restrict__ Cv, int K)
{
    const int m0 = blockIdx.y * GBM;
    const int n0 = blockIdx.x * GBN;          // never straddles 512
    float acc[2][8][4];
    gemm_mainloop(Ah, Al, Bh, Bl, n0, m0, K, acc);
    if (n0 < KVD) {
        const int head = (n0 + ((threadIdx.x >> 5) >> 2) * 64) >> 6;
        epilogue_rope(acc, m0, head, NKV, g_kh, g_kl, cosp, sinp);
    } else {
        epilogue_f32(acc, m0, Cv + (n0 - KVD), KVD);
    }
}

// plain GEMM (O projection)
__global__ __launch_bounds__(256, 2)
void gemm_mma_kernel(const __half* __restrict__ Ah, const __half* __restrict__ Al,
                     const __half* __restrict__ Bh, const __half* __restrict__ Bl,
                     float* __restrict__ C, int M, int N, int K)
{
    const int m0 = blockIdx.y * GBM;
    const int n0 = blockIdx.x * GBN;
    float acc[2][8][4];
    gemm_mainloop(Ah, Al, Bh, Bl, n0, m0, K, acc);
    epilogue_f32(acc, m0, C + n0, N);
}

// =============== Flash attention: R9 (serial K/V load, P in registers) =====
#define QHI_B 0u
#define QLO_B 16384u
#define KHI_B 32768u
#define VHI_B 49152u        // KHI 32768, KLO 40960, VHI 49152, VLO 57344
#define ATTN_SMEM 65536     // 64 KB -> 2 CTAs/SM

__global__ __launch_bounds__(256, 2) void attn_mma_kernel()
{
    extern __shared__ float smf[];
    const uint32_t sb = smem_u32(smf);
    const int qt = (int)gridDim.x - 1 - (int)blockIdx.x;
    const int h = blockIdx.y, b = blockIdx.z;
    const int kvh = h >> 2;
    const int tid = threadIdx.x;
    const int warp = tid >> 5, lane = tid & 31;
    const int q0 = qt * 128;

#pragma unroll
    for (int i = 0; i < 8; i++) {
        int gidx = tid + i * 256;
        int plane = gidx >> 10;
        int c = gidx & 1023;
        int r = c >> 3, q = c & 7;
        const __half* src = (plane ? g_ql : g_qh)
            + (((size_t)(b * SEQ + q0 + r) * NH + h) << 6) + q * 8;
        CP16(sb + QHI_B + (uint32_t)plane * 16384u + SWZ((uint32_t)(r * 128 + q * 16)), src);
    }
    CP_COMMIT();

    const __half* kv_src[8];
    uint32_t kv_dst[8];
    int kv_step[8];
#pragma unroll
    for (int i = 0; i < 8; i++) {
        int gidx = tid + i * 256;
        int plane = gidx >> 9;
        int c = gidx & 511;
        int r = c >> 3, q = c & 7;
        if (plane < 2) {
            kv_src[i] = (plane ? g_kl : g_kh)
                + (((size_t)(b * SEQ + r) * NKV + kvh) << 6) + q * 8;
            kv_step[i] = NKV * HD;
        } else {
            kv_src[i] = ((plane == 3) ? g_vtl : g_vth)
                + ((size_t)((b * NKV + kvh) * HD) + r) * SEQ + q * 8;
            kv_step[i] = 1;
        }
        kv_dst[i] = KHI_B + (uint32_t)plane * 8192u + SWZ((uint32_t)(r * 128 + q * 16));
    }

    const int arowl = lane & 15;
    const int ca = lane >> 4;
    const int lrowb = (lane & 7) + ((lane >> 4) << 3);
    const int cb = (lane >> 3) & 1;
    const int ar = warp * 16 + arowl;
    const uint32_t a_rb = (uint32_t)(ar * 128);
    const int a_rx = ar & 7;
    uint32_t b_rb[4]; int b_rx[4];
#pragma unroll
    for (int bi = 0; bi < 4; bi++) {
        int r = bi * 16 + lrowb;
        b_rb[bi] = (uint32_t)(r * 128); b_rx[bi] = r & 7;
    }

    float m0 = -1e30f, m1 = -1e30f, l0 = 0.f, l1 = 0.f;
    float oacc[8][4];
#pragma unroll
    for (int nt = 0; nt < 8; nt++)
#pragma unroll
        for (int j = 0; j < 4; j++) oacc[nt][j] = 0.f;

    const int rloc = lane >> 2;
    const int qrow0 = q0 + warp * 16 + rloc;
    const int qrow1 = qrow0 + 8;
    const int ktmax = 2 * qt + 1;

    for (int kt = 0; kt <= ktmax; kt++) {
        const int k0 = kt * 64;
        __syncthreads();
#pragma unroll
        for (int i = 0; i < 8; i++)
            CP16(sb + kv_dst[i], kv_src[i] + (size_t)k0 * kv_step[i]);
        CP_COMMIT();
        CP_WAIT0();
        __syncthreads();

        float sacc[8][4];
#pragma unroll
        for (int nt = 0; nt < 8; nt++)
#pragma unroll
            for (int j = 0; j < 4; j++) sacc[nt][j] = 0.f;

#pragma unroll
        for (int ks = 0; ks < 4; ks++) {
            uint32_t qh[4], ql[4];
            uint32_t aoff = a_rb + (uint32_t)((((ks * 2 + ca) ^ a_rx)) << 4);
            LDSM4(qh, sb + QHI_B + aoff);
            LDSM4(ql, sb + QLO_B + aoff);
#pragma unroll
            for (int nt = 0; nt < 4; nt++) {
                uint32_t kh[4], kl[4];
                uint32_t boff = b_rb[nt] + (uint32_t)((((ks * 2 + cb) ^ b_rx[nt])) << 4);
                LDSM4(kh, sb + KHI_B + boff);
                LDSM4(kl, sb + KHI_B + 8192u + boff);
#pragma unroll
                for (int j = 0; j < 2; j++) {
                    int ni = nt * 2 + j;
                    MMA_F16(sacc[ni], qh, kh[j * 2], kh[j * 2 + 1]);
                    MMA_F16(sacc[ni], qh, kl[j * 2], kl[j * 2 + 1]);
                    MMA_F16(sacc[ni], ql, kh[j * 2], kh[j * 2 + 1]);
                }
            }
        }

        const bool domask = (k0 + 63 > q0);
#pragma unroll
        for (int nt = 0; nt < 8; nt++) {
            int keyb = k0 + nt * 8 + (lane & 3) * 2;
#pragma unroll
            for (int j = 0; j < 4; j++) {
                float s = sacc[nt][j] * 0.125f;
                if (domask) {
                    int key = keyb + (j & 1);
                    int qq = (j < 2) ? qrow0 : qrow1;
                    if (key > qq) s = -1e30f;
                }
                sacc[nt][j] = s;
            }
        }
        float mx0 = -1e30f, mx1 = -1e30f;
#pragma unroll
        for (int nt = 0; nt < 8; nt++) {
            mx0 = fmaxf(mx0, fmaxf(sacc[nt][0], sacc[nt][1]));
            mx1 = fmaxf(mx1, fmaxf(sacc[nt][2], sacc[nt][3]));
        }
        mx0 = fmaxf(mx0, __shfl_xor_sync(0xffffffffu, mx0, 1));
        mx0 = fmaxf(mx0, __shfl_xor_sync(0xffffffffu, mx0, 2));
        mx1 = fmaxf(mx1, __shfl_xor_sync(0xffffffffu, mx1, 1));
        mx1 = fmaxf(mx1, __shfl_xor_sync(0xffffffffu, mx1, 2));
        float nm0 = fmaxf(m0, mx0), nm1 = fmaxf(m1, mx1);
        float c0 = __expf(m0 - nm0), c1 = __expf(m1 - nm1);
        m0 = nm0; m1 = nm1;
        float rs0 = 0.f, rs1 = 0.f;
#pragma unroll
        for (int nt = 0; nt < 8; nt++) {
            float p0 = __expf(sacc[nt][0] - nm0);
            float p1 = __expf(sacc[nt][1] - nm0);
            float p2 = __expf(sacc[nt][2] - nm1);
            float p3 = __expf(sacc[nt][3] - nm1);
            sacc[nt][0] = p0; sacc[nt][1] = p1; sacc[nt][2] = p2; sacc[nt][3] = p3;
            rs0 += p0 + p1; rs1 += p2 + p3;
        }
        rs0 += __shfl_xor_sync(0xffffffffu, rs0, 1);
        rs0 += __shfl_xor_sync(0xffffffffu, rs0, 2);
        rs1 += __shfl_xor_sync(0xffffffffu, rs1, 1);
        rs1 += __shfl_xor_sync(0xffffffffu, rs1, 2);
        l0 = l0 * c0 + rs0;
        l1 = l1 * c1 + rs1;
#pragma unroll
        for (int nt = 0; nt < 8; nt++) {
            oacc[nt][0] *= c0; oacc[nt][1] *= c0;
            oacc[nt][2] *= c1; oacc[nt][3] *= c1;
        }

#pragma unroll
        for (int ks = 0; ks < 4; ks++) {
            uint32_t pa[4], pb[4];
            split_pair(sacc[2 * ks][0],     sacc[2 * ks][1],     pa[0], pb[0]);
            split_pair(sacc[2 * ks][2],     sacc[2 * ks][3],     pa[1], pb[1]);
            split_pair(sacc[2 * ks + 1][0], sacc[2 * ks + 1][1], pa[2], pb[2]);
            split_pair(sacc[2 * ks + 1][2], sacc[2 * ks + 1][3], pa[3], pb[3]);
#pragma unroll
            for (int nt = 0; nt < 4; nt++) {
                uint32_t vh[4], vl[4];
                uint32_t boff = b_rb[nt] + (uint32_t)((((ks * 2 + cb) ^ b_rx[nt])) << 4);
                LDSM4(vh, sb + VHI_B + boff);
                LDSM4(vl, sb + VHI_B + 8192u + boff);
#pragma unroll
                for (int j = 0; j < 2; j++) {
                    int ni = nt * 2 + j;
                    MMA_F16(oacc[ni], pa, vh[j * 2], vh[j * 2 + 1]);
                    MMA_F16(oacc[ni], pa, vl[j * 2], vl[j * 2 + 1]);
                    MMA_F16(oacc[ni], pb, vh[j * 2], vh[j * 2 + 1]);
                }
            }
        }
    }

    float inv0 = 1.0f / l0, inv1 = 1.0f / l1;
    size_t o0 = (((size_t)(b * SEQ + qrow0) * NH + h) << 6);
    size_t o1 = (((size_t)(b * SEQ + qrow1) * NH + h) << 6);
#pragma unroll
    for (int nt = 0; nt < 8; nt++) {
        int dim = nt * 8 + (lane & 3) * 2;
        uint32_t hp, lp;
        split_pair(oacc[nt][0] * inv0, oacc[nt][1] * inv0, hp, lp);
        *(uint32_t*)(g_oh + o0 + dim) = hp;
        *(uint32_t*)(g_ol + o0 + dim) = lp;
        split_pair(oacc[nt][2] * inv1, oacc[nt][3] * inv1, hp, lp);
        *(uint32_t*)(g_oh + o1 + dim) = hp;
        *(uint32_t*)(g_ol + o1 + dim) = lp;
    }
}

// ---------------- launch ---------------------------------------------------
extern "C" void kernel_launch(void* const* d_in, const int* in_sizes, int n_in,
                              void* d_out, int out_size)
{
    const float* x    = (const float*)d_in[0];
    const float* cosp = (const float*)d_in[1];
    const float* sinp = (const float*)d_in[2];
    const float* Wq   = (const float*)d_in[3];
    const float* Wk   = (const float*)d_in[4];
    const float* Wv   = (const float*)d_in[5];
    const float* Wo   = (const float*)d_in[6];
    float* out = (float*)d_out;

    float* v;
    __half *xh, *xl, *wqth, *wqtl, *wkvh, *wkvl, *woth, *wotl, *oh, *ol;
    cudaGetSymbolAddress((void**)&v, g_v);
    cudaGetSymbolAddress((void**)&xh, g_xh);
    cudaGetSymbolAddress((void**)&xl, g_xl);
    cudaGetSymbolAddress((void**)&wqth, g_wqth);
    cudaGetSymbolAddress((void**)&wqtl, g_wqtl);
    cudaGetSymbolAddress((void**)&wkvh, g_wkvh);
    cudaGetSymbolAddress((void**)&wkvl, g_wkvl);
    cudaGetSymbolAddress((void**)&woth, g_woth);
    cudaGetSymbolAddress((void**)&wotl, g_wotl);
    cudaGetSymbolAddress((void**)&oh, g_oh);
    cudaGetSymbolAddress((void**)&ol, g_ol);

    cudaFuncSetAttribute(gemm_q_kernel,
                         cudaFuncAttributeMaxDynamicSharedMemorySize, GEMM_SMEM);
    cudaFuncSetAttribute(gemm_kv_kernel,
                         cudaFuncAttributeMaxDynamicSharedMemorySize, GEMM_SMEM);
    cudaFuncSetAttribute(gemm_mma_kernel,
                         cudaFuncAttributeMaxDynamicSharedMemorySize, GEMM_SMEM);
    cudaFuncSetAttribute(attn_mma_kernel,
                         cudaFuncAttributeMaxDynamicSharedMemorySize, ATTN_SMEM);

    dim3 tb(32, 8);
    split_kernel<<<(TOK * D_MODEL / 4 + 255) / 256, 256>>>(x, xh, xl, TOK * D_MODEL / 4);
    wsplit_t_kernel<<<dim3(D_MODEL / 32, D_MODEL / 32), tb>>>(Wq, wqth, wqtl, D_MODEL, D_MODEL, 0);
    wsplit_t_kernel<<<dim3(KVD / 32, D_MODEL / 32), tb>>>(Wk, wkvh, wkvl, D_MODEL, KVD, 0);
    wsplit_t_kernel<<<dim3(KVD / 32, D_MODEL / 32), tb>>>(Wv, wkvh, wkvl, D_MODEL, KVD, KVD);
    wsplit_t_kernel<<<dim3(D_MODEL / 32, D_MODEL / 32), tb>>>(Wo, woth, wotl, D_MODEL, D_MODEL, 0);

    // Q projection with fused RoPE/RMS; fused K|V projection (K fused, V fp32)
    gemm_q_kernel<<<dim3(D_MODEL / GBN, TOK / GBM), 256, GEMM_SMEM>>>(
        xh, xl, wqth, wqtl, cosp, sinp, D_MODEL);
    gemm_kv_kernel<<<dim3((2 * KVD) / GBN, TOK / GBM), 256, GEMM_SMEM>>>(
        xh, xl, wkvh, wkvl, cosp, sinp, v, D_MODEL);

    vsplit_t_kernel<<<dim3(HD / 32, SEQ / 32, BATCH * NKV), tb>>>();

    attn_mma_kernel<<<dim3(SEQ / 128, NH, BATCH), 256, ATTN_SMEM>>>();

    gemm_mma_kernel<<<dim3(D_MODEL / GBN, TOK / GBM), 256, GEMM_SMEM>>>(
        oh, ol, woth, wotl, out, TOK, D_MODEL, D_MODEL);
}

// round 15
// speedup vs baseline: 1.5228x; 1.0120x over previous
#include <cuda_runtime.h>
#include <cuda_fp16.h>
#include <math.h>
#include <stdint.h>

#define D_MODEL 2048
#define NH 32
#define NKV 8
#define HD 64
#define BATCH 2
#define SEQ 2048
#define TOK (BATCH * SEQ)   // 4096
#define KVD (NKV * HD)      // 512

// ---------------- scratch (device globals; no allocation allowed) ----------
__device__ float  g_v[(size_t)TOK * NKV * HD];
__device__ __half g_xh[(size_t)TOK * D_MODEL];
__device__ __half g_xl[(size_t)TOK * D_MODEL];
__device__ __half g_wqth[(size_t)D_MODEL * D_MODEL];
__device__ __half g_wqtl[(size_t)D_MODEL * D_MODEL];
__device__ __half g_wkvh[(size_t)(2 * KVD) * D_MODEL];   // Wk^T | Wv^T hi
__device__ __half g_wkvl[(size_t)(2 * KVD) * D_MODEL];   // lo
__device__ __half g_woth[(size_t)D_MODEL * D_MODEL];
__device__ __half g_wotl[(size_t)D_MODEL * D_MODEL];
__device__ __half g_qh[(size_t)TOK * NH * HD];
__device__ __half g_ql[(size_t)TOK * NH * HD];
__device__ __half g_kh[(size_t)TOK * NKV * HD];
__device__ __half g_kl[(size_t)TOK * NKV * HD];
__device__ __half g_vth[(size_t)BATCH * NKV * HD * SEQ];
__device__ __half g_vtl[(size_t)BATCH * NKV * HD * SEQ];
__device__ __half g_oh[(size_t)TOK * NH * HD];
__device__ __half g_ol[(size_t)TOK * NH * HD];

// ======================= helpers (portable PTX only) ========================
__device__ __forceinline__ uint32_t smem_u32(const void* p) {
    uint32_t a;
    asm("{ .reg .u64 t; cvta.to.shared.u64 t, %1; cvt.u32.u64 %0, t; }"
        : "=r"(a) : "l"(p));
    return a;
}
#define SWZ(o)   ((o) ^ (((o) >> 3) & 0x70))
#define SWZ64(o) ((o) ^ (((o) >> 3) & 0x30))

#define LDSM4(r, a) \
    asm volatile("ldmatrix.sync.aligned.m8n8.x4.shared.b16 {%0,%1,%2,%3}, [%4];" \
        : "=r"((r)[0]), "=r"((r)[1]), "=r"((r)[2]), "=r"((r)[3]) : "r"(a))

#define MMA_F16(c, a, b0, b1) \
    asm volatile("mma.sync.aligned.m16n8k16.row.col.f32.f16.f16.f32 " \
        "{%0,%1,%2,%3}, {%4,%5,%6,%7}, {%8,%9}, {%0,%1,%2,%3};" \
        : "+f"((c)[0]), "+f"((c)[1]), "+f"((c)[2]), "+f"((c)[3]) \
        : "r"((a)[0]), "r"((a)[1]), "r"((a)[2]), "r"((a)[3]), \
          "r"(b0), "r"(b1))

#define CP16(dst, src) \
    asm volatile("cp.async.ca.shared.global [%0], [%1], 16;" \
                 :: "r"(dst), "l"(src) : "memory")
#define CP_COMMIT() asm volatile("cp.async.commit_group;" ::: "memory")
#define CP_WAIT0()  asm volatile("cp.async.wait_group 0;" ::: "memory")

__device__ __forceinline__ uint32_t packh2(__half a, __half b) {
    __half2 t = __halves2half2(a, b);
    return *(uint32_t*)&t;
}
__device__ __forceinline__ void split_pair(float f0, float f1,
                                           uint32_t& hp, uint32_t& lp) {
    __half h0 = __float2half_rn(f0), h1 = __float2half_rn(f1);
    __half l0 = __float2half_rn(f0 - __half2float(h0));
    __half l1 = __float2half_rn(f1 - __half2float(h1));
    hp = packh2(h0, h1); lp = packh2(l0, l1);
}

// ---------------- elementwise split: fp32 -> hi/lo fp16 planes -------------
__global__ void split_kernel(const float* __restrict__ in,
                             __half* __restrict__ hi, __half* __restrict__ lo,
                             int n4)
{
    int i = blockIdx.x * blockDim.x + threadIdx.x;
    if (i >= n4) return;
    float4 v = ((const float4*)in)[i];
    uint32_t h01, l01, h23, l23;
    split_pair(v.x, v.y, h01, l01);
    split_pair(v.z, v.w, h23, l23);
    ((uint2*)hi)[i] = make_uint2(h01, h23);
    ((uint2*)lo)[i] = make_uint2(l01, l23);
}

// ---- transpose + split: W[K,C] fp32 -> rows [rowoff..rowoff+C) of planes --
__global__ void wsplit_t_kernel(const float* __restrict__ in,
                                __half* __restrict__ hi, __half* __restrict__ lo,
                                int R, int C, int rowoff)
{
    __shared__ float t[32][33];
    const int bx = blockIdx.x * 32, by = blockIdx.y * 32;
    const int tx = threadIdx.x, ty = threadIdx.y;
#pragma unroll
    for (int j = 0; j < 32; j += 8)
        t[ty + j][tx] = in[(size_t)(by + ty + j) * C + bx + tx];
    __syncthreads();
#pragma unroll
    for (int j = 0; j < 32; j += 8) {
        float f = t[tx][ty + j];
        __half h = __float2half_rn(f);
        size_t o = (size_t)(rowoff + bx + ty + j) * R + by + tx;
        hi[o] = h;
        lo[o] = __float2half_rn(f - __half2float(h));
    }
}

// ---------------- V: split + transpose -> Vt[b][kvh][dim][seq] -------------
__global__ void vsplit_t_kernel()
{
    __shared__ float t[32][33];
    const int bkv = blockIdx.z;
    const int b = bkv >> 3, kvh = bkv & 7;
    const int s0 = blockIdx.y * 32;
    const int d0 = blockIdx.x * 32;
    const int tx = threadIdx.x, ty = threadIdx.y;
#pragma unroll
    for (int j = 0; j < 32; j += 8)
        t[ty + j][tx] = g_v[(((size_t)(b * SEQ + s0 + ty + j) * NKV + kvh) << 6) + d0 + tx];
    __syncthreads();
#pragma unroll
    for (int j = 0; j < 32; j += 8) {
        float f = t[tx][ty + j];
        __half h = __float2half_rn(f);
        size_t o = ((size_t)(bkv * HD) + d0 + ty + j) * SEQ + s0 + tx;
        g_vth[o] = h;
        g_vtl[o] = __float2half_rn(f - __half2float(h));
    }
}

// ======================= 3xFP16 GEMM mainloop (R9/R13) ======================
#define GBM 128
#define GBN 128
#define GBK 32
#define APL 8192
#define OFF_AHI 0
#define OFF_ALO (APL)
#define OFF_BHI (2 * APL)
#define OFF_BLO (3 * APL)
#define BUFSZ (4 * APL)                // 32 KB / stage
#define GEMM_SMEM (2 * BUFSZ)          // 64 KB

__device__ __forceinline__ void gemm_mainloop(
    const __half* Ah, const __half* Al,
    const __half* Bh, const __half* Bl,
    int n0, int m0, int K, float acc[2][8][4])
{
    extern __shared__ char sm[];
    const uint32_t sb = smem_u32(sm);
    const int tid = threadIdx.x;
    const int wid = tid >> 5, lane = tid & 31;
    const int wm = wid & 3;
    const int wn = wid >> 2;

    const __half* srcs[8];
    uint32_t dsts[8];
#pragma unroll
    for (int i = 0; i < 8; i++) {
        int gidx = tid + i * 256;
        int plane = gidx >> 9;
        int c = gidx & 511;
        int r = c >> 2, q = c & 3;
        const __half* base = (plane == 0) ? Ah : (plane == 1) ? Al
                           : (plane == 2) ? Bh : Bl;
        int row = (plane < 2 ? m0 : n0) + r;
        srcs[i] = base + (size_t)row * K + q * 8;
        dsts[i] = (uint32_t)(plane * APL) + SWZ64((uint32_t)(r * 64 + q * 16));
    }

    const int arowl = lane & 15;
    const int ca = lane >> 4;
    uint32_t a_rb[2]; int a_rx[2];
#pragma unroll
    for (int mi = 0; mi < 2; mi++) {
        int r = wm * 32 + mi * 16 + arowl;
        a_rb[mi] = (uint32_t)(r * 64); a_rx[mi] = (r >> 1) & 3;
    }
    const int lrowb = (lane & 7) + ((lane >> 4) << 3);
    const int cb = (lane >> 3) & 1;
    uint32_t b_rb[4]; int b_rx[4];
#pragma unroll
    for (int bi = 0; bi < 4; bi++) {
        int r = wn * 64 + bi * 16 + lrowb;
        b_rb[bi] = (uint32_t)(r * 64); b_rx[bi] = (r >> 1) & 3;
    }

#pragma unroll
    for (int mi = 0; mi < 2; mi++)
#pragma unroll
        for (int ni = 0; ni < 8; ni++)
#pragma unroll
            for (int j = 0; j < 4; j++) acc[mi][ni][j] = 0.0f;

#pragma unroll
    for (int i = 0; i < 8; i++) CP16(sb + dsts[i], srcs[i]);
    CP_COMMIT();
    CP_WAIT0();
    __syncthreads();

    const int S = K / GBK;
    for (int s = 0; s < S; s++) {
        const uint32_t base = sb + (uint32_t)(s & 1) * BUFSZ;

        if (s + 1 < S) {
            const uint32_t nb = (uint32_t)((s + 1) & 1) * BUFSZ;
            const int k0 = (s + 1) * GBK;
#pragma unroll
            for (int i = 0; i < 8; i++) CP16(sb + nb + dsts[i], srcs[i] + k0);
            CP_COMMIT();
        }

#pragma unroll
        for (int ks = 0; ks < 2; ks++) {
            uint32_t ah[2][4], al[2][4];
#pragma unroll
            for (int mi = 0; mi < 2; mi++) {
                uint32_t off = a_rb[mi] + (uint32_t)((((ks * 2 + ca) ^ a_rx[mi])) << 4);
                LDSM4(ah[mi], base + OFF_AHI + off);
                LDSM4(al[mi], base + OFF_ALO + off);
            }
#pragma unroll
            for (int nt = 0; nt < 4; nt++) {
                uint32_t bh[4], bl[4];
                uint32_t off = b_rb[nt] + (uint32_t)((((ks * 2 + cb) ^ b_rx[nt])) << 4);
                LDSM4(bh, base + OFF_BHI + off);
                LDSM4(bl, base + OFF_BLO + off);
#pragma unroll
                for (int j = 0; j < 2; j++) {
                    int ni = nt * 2 + j;
#pragma unroll
                    for (int mi = 0; mi < 2; mi++) {
                        MMA_F16(acc[mi][ni], ah[mi], bh[j * 2], bh[j * 2 + 1]);
                        MMA_F16(acc[mi][ni], ah[mi], bl[j * 2], bl[j * 2 + 1]);
                        MMA_F16(acc[mi][ni], al[mi], bh[j * 2], bh[j * 2 + 1]);
                    }
                }
            }
        }

        if (s + 1 < S) {
            CP_WAIT0();
            __syncthreads();
        }
    }
}

// fused RoPE + per-head RMSNorm + hi/lo split epilogue.
__device__ __forceinline__ void epilogue_rope(
    float acc[2][8][4], int m0, int head, int nheads,
    __half* __restrict__ hi, __half* __restrict__ lo,
    const float* __restrict__ cosp, const float* __restrict__ sinp)
{
    const int lane = threadIdx.x & 31;
    const int wm = (threadIdx.x >> 5) & 3;
#pragma unroll
    for (int mi = 0; mi < 2; mi++) {
#pragma unroll
        for (int rr = 0; rr < 2; rr++) {
            int row = m0 + wm * 32 + mi * 16 + (lane >> 2) + rr * 8;
            int l = row & (SEQ - 1);
            float o1v[8], o2v[8];
            float ss = 0.f;
#pragma unroll
            for (int ni = 0; ni < 4; ni++) {
#pragma unroll
                for (int j = 0; j < 2; j++) {
                    int d = ni * 8 + (lane & 3) * 2 + j;
                    float x1 = acc[mi][ni][rr * 2 + j];
                    float x2 = acc[mi][ni + 4][rr * 2 + j];
                    float c = cosp[l * 32 + d];
                    float s = sinp[l * 32 + d];
                    float o1 = x1 * c - x2 * s;
                    float o2 = x2 * c + x1 * s;
                    o1v[ni * 2 + j] = o1;
                    o2v[ni * 2 + j] = o2;
                    ss += o1 * o1 + o2 * o2;
                }
            }
            ss += __shfl_xor_sync(0xffffffffu, ss, 1);
            ss += __shfl_xor_sync(0xffffffffu, ss, 2);
            float r = rsqrtf(ss * (1.0f / 64.0f) + 1e-6f);
            size_t base = ((size_t)row * nheads + head) * HD;
#pragma unroll
            for (int ni = 0; ni < 4; ni++) {
                int d = ni * 8 + (lane & 3) * 2;
                uint32_t hp, lp;
                split_pair(o1v[ni * 2] * r, o1v[ni * 2 + 1] * r, hp, lp);
                *(uint32_t*)(hi + base + d) = hp;
                *(uint32_t*)(lo + base + d) = lp;
                split_pair(o2v[ni * 2] * r, o2v[ni * 2 + 1] * r, hp, lp);
                *(uint32_t*)(hi + base + d + 32) = hp;
                *(uint32_t*)(lo + base + d + 32) = lp;
            }
        }
    }
}

__device__ __forceinline__ void epilogue_f32(
    float acc[2][8][4], int m0, float* Cout, int Nout)
{
    const int lane = threadIdx.x & 31;
    const int wid = threadIdx.x >> 5;
    const int wm = wid & 3, wn = wid >> 2;
#pragma unroll
    for (int mi = 0; mi < 2; mi++)
#pragma unroll
        for (int ni = 0; ni < 8; ni++) {
            int row = m0 + wm * 32 + mi * 16 + (lane >> 2);
            int col = wn * 64 + ni * 8 + (lane & 3) * 2;
            *(float2*)(Cout + (size_t)row * Nout + col) =
                make_float2(acc[mi][ni][0], acc[mi][ni][1]);
            *(float2*)(Cout + (size_t)(row + 8) * Nout + col) =
                make_float2(acc[mi][ni][2], acc[mi][ni][3]);
        }
}

__global__ __launch_bounds__(256, 2)
void gemm_q_kernel(const __half* __restrict__ Ah, const __half* __restrict__ Al,
                   const __half* __restrict__ Bh, const __half* __restrict__ Bl,
                   const float* __restrict__ cosp, const float* __restrict__ sinp,
                   int K)
{
    const int m0 = blockIdx.y * GBM;
    const int n0 = blockIdx.x * GBN;
    float acc[2][8][4];
    gemm_mainloop(Ah, Al, Bh, Bl, n0, m0, K, acc);
    const int head = (n0 + ((threadIdx.x >> 5) >> 2) * 64) >> 6;
    epilogue_rope(acc, m0, head, NH, g_qh, g_ql, cosp, sinp);
}

__global__ __launch_bounds__(256, 2)
void gemm_kv_kernel(const __half* __restrict__ Ah, const __half* __restrict__ Al,
                    const __half* __restrict__ Bh, const __half* __restrict__ Bl,
                    const float* __restrict__ cosp, const float* __restrict__ sinp,
                    float* __restrict__ Cv, int K)
{
    const int m0 = blockIdx.y * GBM;
    const int n0 = blockIdx.x * GBN;
    float acc[2][8][4];
    gemm_mainloop(Ah, Al, Bh, Bl, n0, m0, K, acc);
    if (n0 < KVD) {
        const int head = (n0 + ((threadIdx.x >> 5) >> 2) * 64) >> 6;
        epilogue_rope(acc, m0, head, NKV, g_kh, g_kl, cosp, sinp);
    } else {
        epilogue_f32(acc, m0, Cv + (n0 - KVD), KVD);
    }
}

__global__ __launch_bounds__(256, 2)
void gemm_mma_kernel(const __half* __restrict__ Ah, const __half* __restrict__ Al,
                     const __half* __restrict__ Bh, const __half* __restrict__ Bl,
                     float* __restrict__ C, int M, int N, int K)
{
    const int m0 = blockIdx.y * GBM;
    const int n0 = blockIdx.x * GBN;
    float acc[2][8][4];
    gemm_mainloop(Ah, Al, Bh, Bl, n0, m0, K, acc);
    epilogue_f32(acc, m0, C + n0, N);
}

// =============== Flash attention: max-free softmax (RMS-bounded scores) ====
// After RMSNorm, ||q||=||k||=8 => |s|<=8 => exp(s)<=2981: no max subtraction,
// no correction, l accumulates per-thread and is reduced once at the end.
#define QHI_B 0u
#define QLO_B 16384u
#define KHI_B 32768u
#define VHI_B 49152u        // KHI 32768, KLO 40960, VHI 49152, VLO 57344
#define ATTN_SMEM 65536     // 64 KB -> 2 CTAs/SM

__global__ __launch_bounds__(256, 2) void attn_mma_kernel()
{
    extern __shared__ float smf[];
    const uint32_t sb = smem_u32(smf);
    const int qt = (int)gridDim.x - 1 - (int)blockIdx.x;
    const int h = blockIdx.y, b = blockIdx.z;
    const int kvh = h >> 2;
    const int tid = threadIdx.x;
    const int warp = tid >> 5, lane = tid & 31;
    const int q0 = qt * 128;

#pragma unroll
    for (int i = 0; i < 8; i++) {
        int gidx = tid + i * 256;
        int plane = gidx >> 10;
        int c = gidx & 1023;
        int r = c >> 3, q = c & 7;
        const __half* src = (plane ? g_ql : g_qh)
            + (((size_t)(b * SEQ + q0 + r) * NH + h) << 6) + q * 8;
        CP16(sb + QHI_B + (uint32_t)plane * 16384u + SWZ((uint32_t)(r * 128 + q * 16)), src);
    }
    CP_COMMIT();

    const __half* kv_src[8];
    uint32_t kv_dst[8];
    int kv_step[8];
#pragma unroll
    for (int i = 0; i < 8; i++) {
        int gidx = tid + i * 256;
        int plane = gidx >> 9;
        int c = gidx & 511;
        int r = c >> 3, q = c & 7;
        if (plane < 2) {
            kv_src[i] = (plane ? g_kl : g_kh)
                + (((size_t)(b * SEQ + r) * NKV + kvh) << 6) + q * 8;
            kv_step[i] = NKV * HD;
        } else {
            kv_src[i] = ((plane == 3) ? g_vtl : g_vth)
                + ((size_t)((b * NKV + kvh) * HD) + r) * SEQ + q * 8;
            kv_step[i] = 1;
        }
        kv_dst[i] = KHI_B + (uint32_t)plane * 8192u + SWZ((uint32_t)(r * 128 + q * 16));
    }

    const int arowl = lane & 15;
    const int ca = lane >> 4;
    const int lrowb = (lane & 7) + ((lane >> 4) << 3);
    const int cb = (lane >> 3) & 1;
    const int ar = warp * 16 + arowl;
    const uint32_t a_rb = (uint32_t)(ar * 128);
    const int a_rx = ar & 7;
    uint32_t b_rb[4]; int b_rx[4];
#pragma unroll
    for (int bi = 0; bi < 4; bi++) {
        int r = bi * 16 + lrowb;
        b_rb[bi] = (uint32_t)(r * 128); b_rx[bi] = r & 7;
    }

    float l0 = 0.f, l1 = 0.f;          // per-thread partial row sums
    float oacc[8][4];
#pragma unroll
    for (int nt = 0; nt < 8; nt++)
#pragma unroll
        for (int j = 0; j < 4; j++) oacc[nt][j] = 0.f;

    const int rloc = lane >> 2;
    const int qrow0 = q0 + warp * 16 + rloc;
    const int qrow1 = qrow0 + 8;
    const int ktmax = 2 * qt + 1;

    for (int kt = 0; kt <= ktmax; kt++) {
        const int k0 = kt * 64;
        __syncthreads();
#pragma unroll
        for (int i = 0; i < 8; i++)
            CP16(sb + kv_dst[i], kv_src[i] + (size_t)k0 * kv_step[i]);
        CP_COMMIT();
        CP_WAIT0();
        __syncthreads();

        // ---- S = Q @ K^T ----
        float sacc[8][4];
#pragma unroll
        for (int nt = 0; nt < 8; nt++)
#pragma unroll
            for (int j = 0; j < 4; j++) sacc[nt][j] = 0.f;

#pragma unroll
        for (int ks = 0; ks < 4; ks++) {
            uint32_t qh[4], ql[4];
            uint32_t aoff = a_rb + (uint32_t)((((ks * 2 + ca) ^ a_rx)) << 4);
            LDSM4(qh, sb + QHI_B + aoff);
            LDSM4(ql, sb + QLO_B + aoff);
#pragma unroll
            for (int nt = 0; nt < 4; nt++) {
                uint32_t kh[4], kl[4];
                uint32_t boff = b_rb[nt] + (uint32_t)((((ks * 2 + cb) ^ b_rx[nt])) << 4);
                LDSM4(kh, sb + KHI_B + boff);
                LDSM4(kl, sb + KHI_B + 8192u + boff);
#pragma unroll
                for (int j = 0; j < 2; j++) {
                    int ni = nt * 2 + j;
                    MMA_F16(sacc[ni], qh, kh[j * 2], kh[j * 2 + 1]);
                    MMA_F16(sacc[ni], qh, kl[j * 2], kl[j * 2 + 1]);
                    MMA_F16(sacc[ni], ql, kh[j * 2], kh[j * 2 + 1]);
                }
            }
        }

        // ---- max-free softmax: p = exp(s/8), mask -> 0 ----
        const bool domask = (k0 + 63 > q0);
#pragma unroll
        for (int nt = 0; nt < 8; nt++) {
            int keyb = k0 + nt * 8 + (lane & 3) * 2;
#pragma unroll
            for (int j = 0; j < 4; j++) {
                float s = sacc[nt][j] * 0.125f;
                if (domask) {
                    int key = keyb + (j & 1);
                    int qq = (j < 2) ? qrow0 : qrow1;
                    if (key > qq) s = -1e30f;
                }
                float p = __expf(s);
                sacc[nt][j] = p;
            }
            l0 += sacc[nt][0] + sacc[nt][1];
            l1 += sacc[nt][2] + sacc[nt][3];
        }

        // ---- O += P @ V  (P packed from registers) ----
#pragma unroll
        for (int ks = 0; ks < 4; ks++) {
            uint32_t pa[4], pb[4];
            split_pair(sacc[2 * ks][0],     sacc[2 * ks][1],     pa[0], pb[0]);
            split_pair(sacc[2 * ks][2],     sacc[2 * ks][3],     pa[1], pb[1]);
            split_pair(sacc[2 * ks + 1][0], sacc[2 * ks + 1][1], pa[2], pb[2]);
            split_pair(sacc[2 * ks + 1][2], sacc[2 * ks + 1][3], pa[3], pb[3]);
#pragma unroll
            for (int nt = 0; nt < 4; nt++) {
                uint32_t vh[4], vl[4];
                uint32_t boff = b_rb[nt] + (uint32_t)((((ks * 2 + cb) ^ b_rx[nt])) << 4);
                LDSM4(vh, sb + VHI_B + boff);
                LDSM4(vl, sb + VHI_B + 8192u + boff);
#pragma unroll
                for (int j = 0; j < 2; j++) {
                    int ni = nt * 2 + j;
                    MMA_F16(oacc[ni], pa, vh[j * 2], vh[j * 2 + 1]);
                    MMA_F16(oacc[ni], pa, vl[j * 2], vl[j * 2 + 1]);
                    MMA_F16(oacc[ni], pb, vh[j * 2], vh[j * 2 + 1]);
                }
            }
        }
    }

    // ---- single row-sum reduction + normalize + split ----
    l0 += __shfl_xor_sync(0xffffffffu, l0, 1);
    l0 += __shfl_xor_sync(0xffffffffu, l0, 2);
    l1 += __shfl_xor_sync(0xffffffffu, l1, 1);
    l1 += __shfl_xor_sync(0xffffffffu, l1, 2);
    float inv0 = 1.0f / l0, inv1 = 1.0f / l1;
    size_t o0 = (((size_t)(b * SEQ + qrow0) * NH + h) << 6);
    size_t o1 = (((size_t)(b * SEQ + qrow1) * NH + h) << 6);
#pragma unroll
    for (int nt = 0; nt < 8; nt++) {
        int dim = nt * 8 + (lane & 3) * 2;
        uint32_t hp, lp;
        split_pair(oacc[nt][0] * inv0, oacc[nt][1] * inv0, hp, lp);
        *(uint32_t*)(g_oh + o0 + dim) = hp;
        *(uint32_t*)(g_ol + o0 + dim) = lp;
        split_pair(oacc[nt][2] * inv1, oacc[nt][3] * inv1, hp, lp);
        *(uint32_t*)(g_oh + o1 + dim) = hp;
        *(uint32_t*)(g_ol + o1 + dim) = lp;
    }
}

// ---------------- launch ---------------------------------------------------
extern "C" void kernel_launch(void* const* d_in, const int* in_sizes, int n_in,
                              void* d_out, int out_size)
{
    const float* x    = (const float*)d_in[0];
    const float* cosp = (const float*)d_in[1];
    const float* sinp = (const float*)d_in[2];
    const float* Wq   = (const float*)d_in[3];
    const float* Wk   = (const float*)d_in[4];
    const float* Wv   = (const float*)d_in[5];
    const float* Wo   = (const float*)d_in[6];
    float* out = (float*)d_out;

    float* v;
    __half *xh, *xl, *wqth, *wqtl, *wkvh, *wkvl, *woth, *wotl, *oh, *ol;
    cudaGetSymbolAddress((void**)&v, g_v);
    cudaGetSymbolAddress((void**)&xh, g_xh);
    cudaGetSymbolAddress((void**)&xl, g_xl);
    cudaGetSymbolAddress((void**)&wqth, g_wqth);
    cudaGetSymbolAddress((void**)&wqtl, g_wqtl);
    cudaGetSymbolAddress((void**)&wkvh, g_wkvh);
    cudaGetSymbolAddress((void**)&wkvl, g_wkvl);
    cudaGetSymbolAddress((void**)&woth, g_woth);
    cudaGetSymbolAddress((void**)&wotl, g_wotl);
    cudaGetSymbolAddress((void**)&oh, g_oh);
    cudaGetSymbolAddress((void**)&ol, g_ol);

    cudaFuncSetAttribute(gemm_q_kernel,
                         cudaFuncAttributeMaxDynamicSharedMemorySize, GEMM_SMEM);
    cudaFuncSetAttribute(gemm_kv_kernel,
                         cudaFuncAttributeMaxDynamicSharedMemorySize, GEMM_SMEM);
    cudaFuncSetAttribute(gemm_mma_kernel,
                         cudaFuncAttributeMaxDynamicSharedMemorySize, GEMM_SMEM);
    cudaFuncSetAttribute(attn_mma_kernel,
                         cudaFuncAttributeMaxDynamicSharedMemorySize, ATTN_SMEM);

    dim3 tb(32, 8);
    split_kernel<<<(TOK * D_MODEL / 4 + 255) / 256, 256>>>(x, xh, xl, TOK * D_MODEL / 4);
    wsplit_t_kernel<<<dim3(D_MODEL / 32, D_MODEL / 32), tb>>>(Wq, wqth, wqtl, D_MODEL, D_MODEL, 0);
    wsplit_t_kernel<<<dim3(KVD / 32, D_MODEL / 32), tb>>>(Wk, wkvh, wkvl, D_MODEL, KVD, 0);
    wsplit_t_kernel<<<dim3(KVD / 32, D_MODEL / 32), tb>>>(Wv, wkvh, wkvl, D_MODEL, KVD, KVD);
    wsplit_t_kernel<<<dim3(D_MODEL / 32, D_MODEL / 32), tb>>>(Wo, woth, wotl, D_MODEL, D_MODEL, 0);

    gemm_q_kernel<<<dim3(D_MODEL / GBN, TOK / GBM), 256, GEMM_SMEM>>>(
        xh, xl, wqth, wqtl, cosp, sinp, D_MODEL);
    gemm_kv_kernel<<<dim3((2 * KVD) / GBN, TOK / GBM), 256, GEMM_SMEM>>>(
        xh, xl, wkvh, wkvl, cosp, sinp, v, D_MODEL);

    vsplit_t_kernel<<<dim3(HD / 32, SEQ / 32, BATCH * NKV), tb>>>();

    attn_mma_kernel<<<dim3(SEQ / 128, NH, BATCH), 256, ATTN_SMEM>>>();

    gemm_mma_kernel<<<dim3(D_MODEL / GBN, TOK / GBM), 256, GEMM_SMEM>>>(
        oh, ol, woth, wotl, out, TOK, D_MODEL, D_MODEL);
}

// round 16
// speedup vs baseline: 1.5580x; 1.0231x over previous
#include <cuda_runtime.h>
#include <cuda_fp16.h>
#include <math.h>
#include <stdint.h>

#define D_MODEL 2048
#define NH 32
#define NKV 8
#define HD 64
#define BATCH 2
#define SEQ 2048
#define TOK (BATCH * SEQ)   // 4096
#define KVD (NKV * HD)      // 512

// ---------------- scratch (device globals; no allocation allowed) ----------
__device__ float  g_v[(size_t)TOK * NKV * HD];
__device__ __half g_xh[(size_t)TOK * D_MODEL];
__device__ __half g_xl[(size_t)TOK * D_MODEL];
__device__ __half g_wqth[(size_t)D_MODEL * D_MODEL];
__device__ __half g_wqtl[(size_t)D_MODEL * D_MODEL];
__device__ __half g_wkvh[(size_t)(2 * KVD) * D_MODEL];   // Wk^T | Wv^T hi
__device__ __half g_wkvl[(size_t)(2 * KVD) * D_MODEL];   // lo
__device__ __half g_woth[(size_t)D_MODEL * D_MODEL];
__device__ __half g_wotl[(size_t)D_MODEL * D_MODEL];
__device__ __half g_qh[(size_t)TOK * NH * HD];
__device__ __half g_ql[(size_t)TOK * NH * HD];
__device__ __half g_kh[(size_t)TOK * NKV * HD];
__device__ __half g_kl[(size_t)TOK * NKV * HD];
__device__ __half g_vth[(size_t)BATCH * NKV * HD * SEQ];
__device__ __half g_vtl[(size_t)BATCH * NKV * HD * SEQ];
__device__ __half g_oh[(size_t)TOK * NH * HD];
__device__ __half g_ol[(size_t)TOK * NH * HD];

// ======================= helpers (portable PTX only) ========================
__device__ __forceinline__ uint32_t smem_u32(const void* p) {
    uint32_t a;
    asm("{ .reg .u64 t; cvta.to.shared.u64 t, %1; cvt.u32.u64 %0, t; }"
        : "=r"(a) : "l"(p));
    return a;
}
#define SWZ(o)   ((o) ^ (((o) >> 3) & 0x70))
#define SWZ64(o) ((o) ^ (((o) >> 3) & 0x30))

#define LDSM4(r, a) \
    asm volatile("ldmatrix.sync.aligned.m8n8.x4.shared.b16 {%0,%1,%2,%3}, [%4];" \
        : "=r"((r)[0]), "=r"((r)[1]), "=r"((r)[2]), "=r"((r)[3]) : "r"(a))

#define MMA_F16(c, a, b0, b1) \
    asm volatile("mma.sync.aligned.m16n8k16.row.col.f32.f16.f16.f32 " \
        "{%0,%1,%2,%3}, {%4,%5,%6,%7}, {%8,%9}, {%0,%1,%2,%3};" \
        : "+f"((c)[0]), "+f"((c)[1]), "+f"((c)[2]), "+f"((c)[3]) \
        : "r"((a)[0]), "r"((a)[1]), "r"((a)[2]), "r"((a)[3]), \
          "r"(b0), "r"(b1))

#define CP16(dst, src) \
    asm volatile("cp.async.ca.shared.global [%0], [%1], 16;" \
                 :: "r"(dst), "l"(src) : "memory")
#define CP_COMMIT() asm volatile("cp.async.commit_group;" ::: "memory")
#define CP_WAIT0()  asm volatile("cp.async.wait_group 0;" ::: "memory")

__device__ __forceinline__ uint32_t packh2(__half a, __half b) {
    __half2 t = __halves2half2(a, b);
    return *(uint32_t*)&t;
}
__device__ __forceinline__ void split_pair(float f0, float f1,
                                           uint32_t& hp, uint32_t& lp) {
    __half h0 = __float2half_rn(f0), h1 = __float2half_rn(f1);
    __half l0 = __float2half_rn(f0 - __half2float(h0));
    __half l1 = __float2half_rn(f1 - __half2float(h1));
    hp = packh2(h0, h1); lp = packh2(l0, l1);
}

// ---------------- elementwise split: fp32 -> hi/lo fp16 planes -------------
__global__ void split_kernel(const float* __restrict__ in,
                             __half* __restrict__ hi, __half* __restrict__ lo,
                             int n4)
{
    int i = blockIdx.x * blockDim.x + threadIdx.x;
    if (i >= n4) return;
    float4 v = ((const float4*)in)[i];
    uint32_t h01, l01, h23, l23;
    split_pair(v.x, v.y, h01, l01);
    split_pair(v.z, v.w, h23, l23);
    ((uint2*)hi)[i] = make_uint2(h01, h23);
    ((uint2*)lo)[i] = make_uint2(l01, l23);
}

// ---- transpose + split: W[K,C] fp32 -> rows [rowoff..rowoff+C) of planes --
__global__ void wsplit_t_kernel(const float* __restrict__ in,
                                __half* __restrict__ hi, __half* __restrict__ lo,
                                int R, int C, int rowoff)
{
    __shared__ float t[32][33];
    const int bx = blockIdx.x * 32, by = blockIdx.y * 32;
    const int tx = threadIdx.x, ty = threadIdx.y;
#pragma unroll
    for (int j = 0; j < 32; j += 8)
        t[ty + j][tx] = in[(size_t)(by + ty + j) * C + bx + tx];
    __syncthreads();
#pragma unroll
    for (int j = 0; j < 32; j += 8) {
        float f = t[tx][ty + j];
        __half h = __float2half_rn(f);
        size_t o = (size_t)(rowoff + bx + ty + j) * R + by + tx;
        hi[o] = h;
        lo[o] = __float2half_rn(f - __half2float(h));
    }
}

// ---------------- V: split + transpose -> Vt[b][kvh][dim][seq] -------------
__global__ void vsplit_t_kernel()
{
    __shared__ float t[32][33];
    const int bkv = blockIdx.z;
    const int b = bkv >> 3, kvh = bkv & 7;
    const int s0 = blockIdx.y * 32;
    const int d0 = blockIdx.x * 32;
    const int tx = threadIdx.x, ty = threadIdx.y;
#pragma unroll
    for (int j = 0; j < 32; j += 8)
        t[ty + j][tx] = g_v[(((size_t)(b * SEQ + s0 + ty + j) * NKV + kvh) << 6) + d0 + tx];
    __syncthreads();
#pragma unroll
    for (int j = 0; j < 32; j += 8) {
        float f = t[tx][ty + j];
        __half h = __float2half_rn(f);
        size_t o = ((size_t)(bkv * HD) + d0 + ty + j) * SEQ + s0 + tx;
        g_vth[o] = h;
        g_vtl[o] = __float2half_rn(f - __half2float(h));
    }
}

// ======================= 3xFP16 GEMM mainloop (R9/R13) ======================
#define GBM 128
#define GBN 128
#define GBK 32
#define APL 8192
#define OFF_AHI 0
#define OFF_ALO (APL)
#define OFF_BHI (2 * APL)
#define OFF_BLO (3 * APL)
#define BUFSZ (4 * APL)                // 32 KB / stage
#define GEMM_SMEM (2 * BUFSZ)          // 64 KB

__device__ __forceinline__ void gemm_mainloop(
    const __half* Ah, const __half* Al,
    const __half* Bh, const __half* Bl,
    int n0, int m0, int K, float acc[2][8][4])
{
    extern __shared__ char sm[];
    const uint32_t sb = smem_u32(sm);
    const int tid = threadIdx.x;
    const int wid = tid >> 5, lane = tid & 31;
    const int wm = wid & 3;
    const int wn = wid >> 2;

    const __half* srcs[8];
    uint32_t dsts[8];
#pragma unroll
    for (int i = 0; i < 8; i++) {
        int gidx = tid + i * 256;
        int plane = gidx >> 9;
        int c = gidx & 511;
        int r = c >> 2, q = c & 3;
        const __half* base = (plane == 0) ? Ah : (plane == 1) ? Al
                           : (plane == 2) ? Bh : Bl;
        int row = (plane < 2 ? m0 : n0) + r;
        srcs[i] = base + (size_t)row * K + q * 8;
        dsts[i] = (uint32_t)(plane * APL) + SWZ64((uint32_t)(r * 64 + q * 16));
    }

    const int arowl = lane & 15;
    const int ca = lane >> 4;
    uint32_t a_rb[2]; int a_rx[2];
#pragma unroll
    for (int mi = 0; mi < 2; mi++) {
        int r = wm * 32 + mi * 16 + arowl;
        a_rb[mi] = (uint32_t)(r * 64); a_rx[mi] = (r >> 1) & 3;
    }
    const int lrowb = (lane & 7) + ((lane >> 4) << 3);
    const int cb = (lane >> 3) & 1;
    uint32_t b_rb[4]; int b_rx[4];
#pragma unroll
    for (int bi = 0; bi < 4; bi++) {
        int r = wn * 64 + bi * 16 + lrowb;
        b_rb[bi] = (uint32_t)(r * 64); b_rx[bi] = (r >> 1) & 3;
    }

#pragma unroll
    for (int mi = 0; mi < 2; mi++)
#pragma unroll
        for (int ni = 0; ni < 8; ni++)
#pragma unroll
            for (int j = 0; j < 4; j++) acc[mi][ni][j] = 0.0f;

#pragma unroll
    for (int i = 0; i < 8; i++) CP16(sb + dsts[i], srcs[i]);
    CP_COMMIT();
    CP_WAIT0();
    __syncthreads();

    const int S = K / GBK;
    for (int s = 0; s < S; s++) {
        const uint32_t base = sb + (uint32_t)(s & 1) * BUFSZ;

        if (s + 1 < S) {
            const uint32_t nb = (uint32_t)((s + 1) & 1) * BUFSZ;
            const int k0 = (s + 1) * GBK;
#pragma unroll
            for (int i = 0; i < 8; i++) CP16(sb + nb + dsts[i], srcs[i] + k0);
            CP_COMMIT();
        }

#pragma unroll
        for (int ks = 0; ks < 2; ks++) {
            uint32_t ah[2][4], al[2][4];
#pragma unroll
            for (int mi = 0; mi < 2; mi++) {
                uint32_t off = a_rb[mi] + (uint32_t)((((ks * 2 + ca) ^ a_rx[mi])) << 4);
                LDSM4(ah[mi], base + OFF_AHI + off);
                LDSM4(al[mi], base + OFF_ALO + off);
            }
#pragma unroll
            for (int nt = 0; nt < 4; nt++) {
                uint32_t bh[4], bl[4];
                uint32_t off = b_rb[nt] + (uint32_t)((((ks * 2 + cb) ^ b_rx[nt])) << 4);
                LDSM4(bh, base + OFF_BHI + off);
                LDSM4(bl, base + OFF_BLO + off);
#pragma unroll
                for (int j = 0; j < 2; j++) {
                    int ni = nt * 2 + j;
#pragma unroll
                    for (int mi = 0; mi < 2; mi++) {
                        MMA_F16(acc[mi][ni], ah[mi], bh[j * 2], bh[j * 2 + 1]);
                        MMA_F16(acc[mi][ni], ah[mi], bl[j * 2], bl[j * 2 + 1]);
                        MMA_F16(acc[mi][ni], al[mi], bh[j * 2], bh[j * 2 + 1]);
                    }
                }
            }
        }

        if (s + 1 < S) {
            CP_WAIT0();
            __syncthreads();
        }
    }
}

// fused RoPE + per-head RMSNorm + hi/lo split epilogue.
__device__ __forceinline__ void epilogue_rope(
    float acc[2][8][4], int m0, int head, int nheads,
    __half* __restrict__ hi, __half* __restrict__ lo,
    const float* __restrict__ cosp, const float* __restrict__ sinp)
{
    const int lane = threadIdx.x & 31;
    const int wm = (threadIdx.x >> 5) & 3;
#pragma unroll
    for (int mi = 0; mi < 2; mi++) {
#pragma unroll
        for (int rr = 0; rr < 2; rr++) {
            int row = m0 + wm * 32 + mi * 16 + (lane >> 2) + rr * 8;
            int l = row & (SEQ - 1);
            float o1v[8], o2v[8];
            float ss = 0.f;
#pragma unroll
            for (int ni = 0; ni < 4; ni++) {
#pragma unroll
                for (int j = 0; j < 2; j++) {
                    int d = ni * 8 + (lane & 3) * 2 + j;
                    float x1 = acc[mi][ni][rr * 2 + j];
                    float x2 = acc[mi][ni + 4][rr * 2 + j];
                    float c = cosp[l * 32 + d];
                    float s = sinp[l * 32 + d];
                    float o1 = x1 * c - x2 * s;
                    float o2 = x2 * c + x1 * s;
                    o1v[ni * 2 + j] = o1;
                    o2v[ni * 2 + j] = o2;
                    ss += o1 * o1 + o2 * o2;
                }
            }
            ss += __shfl_xor_sync(0xffffffffu, ss, 1);
            ss += __shfl_xor_sync(0xffffffffu, ss, 2);
            float r = rsqrtf(ss * (1.0f / 64.0f) + 1e-6f);
            size_t base = ((size_t)row * nheads + head) * HD;
#pragma unroll
            for (int ni = 0; ni < 4; ni++) {
                int d = ni * 8 + (lane & 3) * 2;
                uint32_t hp, lp;
                split_pair(o1v[ni * 2] * r, o1v[ni * 2 + 1] * r, hp, lp);
                *(uint32_t*)(hi + base + d) = hp;
                *(uint32_t*)(lo + base + d) = lp;
                split_pair(o2v[ni * 2] * r, o2v[ni * 2 + 1] * r, hp, lp);
                *(uint32_t*)(hi + base + d + 32) = hp;
                *(uint32_t*)(lo + base + d + 32) = lp;
            }
        }
    }
}

__device__ __forceinline__ void epilogue_f32(
    float acc[2][8][4], int m0, float* Cout, int Nout)
{
    const int lane = threadIdx.x & 31;
    const int wid = threadIdx.x >> 5;
    const int wm = wid & 3, wn = wid >> 2;
#pragma unroll
    for (int mi = 0; mi < 2; mi++)
#pragma unroll
        for (int ni = 0; ni < 8; ni++) {
            int row = m0 + wm * 32 + mi * 16 + (lane >> 2);
            int col = wn * 64 + ni * 8 + (lane & 3) * 2;
            *(float2*)(Cout + (size_t)row * Nout + col) =
                make_float2(acc[mi][ni][0], acc[mi][ni][1]);
            *(float2*)(Cout + (size_t)(row + 8) * Nout + col) =
                make_float2(acc[mi][ni][2], acc[mi][ni][3]);
        }
}

// Merged Q|K|V projection in ONE launch. grid.x = 24 N-tiles:
//   0..15  -> Q (B = wqt planes),  rope epilogue -> g_q{h,l}  (NH heads)
//   16..19 -> K (B = wkv rows 0..511), rope epilogue -> g_k{h,l} (NKV heads)
//   20..23 -> V (B = wkv rows 512..1023), fp32 epilogue -> g_v
// Output layouts identical to the split-launch version.
__global__ __launch_bounds__(256, 2)
void gemm_qkv_kernel(const __half* __restrict__ Ah, const __half* __restrict__ Al,
                     const __half* __restrict__ Bqh, const __half* __restrict__ Bql,
                     const __half* __restrict__ Bkvh, const __half* __restrict__ Bkvl,
                     const float* __restrict__ cosp, const float* __restrict__ sinp,
                     float* __restrict__ Cv, int K)
{
    const int m0 = blockIdx.y * GBM;
    const int nx = blockIdx.x;
    float acc[2][8][4];
    if (nx < 16) {
        const int n0 = nx * GBN;
        gemm_mainloop(Ah, Al, Bqh, Bql, n0, m0, K, acc);
        const int head = (n0 + ((threadIdx.x >> 5) >> 2) * 64) >> 6;
        epilogue_rope(acc, m0, head, NH, g_qh, g_ql, cosp, sinp);
    } else {
        const int n0 = (nx - 16) * GBN;       // 0..896, never straddles 512
        gemm_mainloop(Ah, Al, Bkvh, Bkvl, n0, m0, K, acc);
        if (n0 < KVD) {
            const int head = (n0 + ((threadIdx.x >> 5) >> 2) * 64) >> 6;
            epilogue_rope(acc, m0, head, NKV, g_kh, g_kl, cosp, sinp);
        } else {
            epilogue_f32(acc, m0, Cv + (n0 - KVD), KVD);
        }
    }
}

// plain GEMM (O projection)
__global__ __launch_bounds__(256, 2)
void gemm_mma_kernel(const __half* __restrict__ Ah, const __half* __restrict__ Al,
                     const __half* __restrict__ Bh, const __half* __restrict__ Bl,
                     float* __restrict__ C, int M, int N, int K)
{
    const int m0 = blockIdx.y * GBM;
    const int n0 = blockIdx.x * GBN;
    float acc[2][8][4];
    gemm_mainloop(Ah, Al, Bh, Bl, n0, m0, K, acc);
    epilogue_f32(acc, m0, C + n0, N);
}

// =============== Flash attention: max-free softmax (RMS-bounded scores) ====
#define QHI_B 0u
#define QLO_B 16384u
#define KHI_B 32768u
#define VHI_B 49152u        // KHI 32768, KLO 40960, VHI 49152, VLO 57344
#define ATTN_SMEM 65536     // 64 KB -> 2 CTAs/SM

__global__ __launch_bounds__(256, 2) void attn_mma_kernel()
{
    extern __shared__ float smf[];
    const uint32_t sb = smem_u32(smf);
    const int qt = (int)gridDim.x - 1 - (int)blockIdx.x;
    const int h = blockIdx.y, b = blockIdx.z;
    const int kvh = h >> 2;
    const int tid = threadIdx.x;
    const int warp = tid >> 5, lane = tid & 31;
    const int q0 = qt * 128;

#pragma unroll
    for (int i = 0; i < 8; i++) {
        int gidx = tid + i * 256;
        int plane = gidx >> 10;
        int c = gidx & 1023;
        int r = c >> 3, q = c & 7;
        const __half* src = (plane ? g_ql : g_qh)
            + (((size_t)(b * SEQ + q0 + r) * NH + h) << 6) + q * 8;
        CP16(sb + QHI_B + (uint32_t)plane * 16384u + SWZ((uint32_t)(r * 128 + q * 16)), src);
    }
    CP_COMMIT();

    const __half* kv_src[8];
    uint32_t kv_dst[8];
    int kv_step[8];
#pragma unroll
    for (int i = 0; i < 8; i++) {
        int gidx = tid + i * 256;
        int plane = gidx >> 9;
        int c = gidx & 511;
        int r = c >> 3, q = c & 7;
        if (plane < 2) {
            kv_src[i] = (plane ? g_kl : g_kh)
                + (((size_t)(b * SEQ + r) * NKV + kvh) << 6) + q * 8;
            kv_step[i] = NKV * HD;
        } else {
            kv_src[i] = ((plane == 3) ? g_vtl : g_vth)
                + ((size_t)((b * NKV + kvh) * HD) + r) * SEQ + q * 8;
            kv_step[i] = 1;
        }
        kv_dst[i] = KHI_B + (uint32_t)plane * 8192u + SWZ((uint32_t)(r * 128 + q * 16));
    }

    const int arowl = lane & 15;
    const int ca = lane >> 4;
    const int lrowb = (lane & 7) + ((lane >> 4) << 3);
    const int cb = (lane >> 3) & 1;
    const int ar = warp * 16 + arowl;
    const uint32_t a_rb = (uint32_t)(ar * 128);
    const int a_rx = ar & 7;
    uint32_t b_rb[4]; int b_rx[4];
#pragma unroll
    for (int bi = 0; bi < 4; bi++) {
        int r = bi * 16 + lrowb;
        b_rb[bi] = (uint32_t)(r * 128); b_rx[bi] = r & 7;
    }

    float l0 = 0.f, l1 = 0.f;
    float oacc[8][4];
#pragma unroll
    for (int nt = 0; nt < 8; nt++)
#pragma unroll
        for (int j = 0; j < 4; j++) oacc[nt][j] = 0.f;

    const int rloc = lane >> 2;
    const int qrow0 = q0 + warp * 16 + rloc;
    const int qrow1 = qrow0 + 8;
    const int ktmax = 2 * qt + 1;

    for (int kt = 0; kt <= ktmax; kt++) {
        const int k0 = kt * 64;
        __syncthreads();
#pragma unroll
        for (int i = 0; i < 8; i++)
            CP16(sb + kv_dst[i], kv_src[i] + (size_t)k0 * kv_step[i]);
        CP_COMMIT();
        CP_WAIT0();
        __syncthreads();

        float sacc[8][4];
#pragma unroll
        for (int nt = 0; nt < 8; nt++)
#pragma unroll
            for (int j = 0; j < 4; j++) sacc[nt][j] = 0.f;

#pragma unroll
        for (int ks = 0; ks < 4; ks++) {
            uint32_t qh[4], ql[4];
            uint32_t aoff = a_rb + (uint32_t)((((ks * 2 + ca) ^ a_rx)) << 4);
            LDSM4(qh, sb + QHI_B + aoff);
            LDSM4(ql, sb + QLO_B + aoff);
#pragma unroll
            for (int nt = 0; nt < 4; nt++) {
                uint32_t kh[4], kl[4];
                uint32_t boff = b_rb[nt] + (uint32_t)((((ks * 2 + cb) ^ b_rx[nt])) << 4);
                LDSM4(kh, sb + KHI_B + boff);
                LDSM4(kl, sb + KHI_B + 8192u + boff);
#pragma unroll
                for (int j = 0; j < 2; j++) {
                    int ni = nt * 2 + j;
                    MMA_F16(sacc[ni], qh, kh[j * 2], kh[j * 2 + 1]);
                    MMA_F16(sacc[ni], qh, kl[j * 2], kl[j * 2 + 1]);
                    MMA_F16(sacc[ni], ql, kh[j * 2], kh[j * 2 + 1]);
                }
            }
        }

        const bool domask = (k0 + 63 > q0);
#pragma unroll
        for (int nt = 0; nt < 8; nt++) {
            int keyb = k0 + nt * 8 + (lane & 3) * 2;
#pragma unroll
            for (int j = 0; j < 4; j++) {
                float s = sacc[nt][j] * 0.125f;
                if (domask) {
                    int key = keyb + (j & 1);
                    int qq = (j < 2) ? qrow0 : qrow1;
                    if (key > qq) s = -1e30f;
                }
                float p = __expf(s);
                sacc[nt][j] = p;
            }
            l0 += sacc[nt][0] + sacc[nt][1];
            l1 += sacc[nt][2] + sacc[nt][3];
        }

#pragma unroll
        for (int ks = 0; ks < 4; ks++) {
            uint32_t pa[4], pb[4];
            split_pair(sacc[2 * ks][0],     sacc[2 * ks][1],     pa[0], pb[0]);
            split_pair(sacc[2 * ks][2],     sacc[2 * ks][3],     pa[1], pb[1]);
            split_pair(sacc[2 * ks + 1][0], sacc[2 * ks + 1][1], pa[2], pb[2]);
            split_pair(sacc[2 * ks + 1][2], sacc[2 * ks + 1][3], pa[3], pb[3]);
#pragma unroll
            for (int nt = 0; nt < 4; nt++) {
                uint32_t vh[4], vl[4];
                uint32_t boff = b_rb[nt] + (uint32_t)((((ks * 2 + cb) ^ b_rx[nt])) << 4);
                LDSM4(vh, sb + VHI_B + boff);
                LDSM4(vl, sb + VHI_B + 8192u + boff);
#pragma unroll
                for (int j = 0; j < 2; j++) {
                    int ni = nt * 2 + j;
                    MMA_F16(oacc[ni], pa, vh[j * 2], vh[j * 2 + 1]);
                    MMA_F16(oacc[ni], pa, vl[j * 2], vl[j * 2 + 1]);
                    MMA_F16(oacc[ni], pb, vh[j * 2], vh[j * 2 + 1]);
                }
            }
        }
    }

    l0 += __shfl_xor_sync(0xffffffffu, l0, 1);
    l0 += __shfl_xor_sync(0xffffffffu, l0, 2);
    l1 += __shfl_xor_sync(0xffffffffu, l1, 1);
    l1 += __shfl_xor_sync(0xffffffffu, l1, 2);
    float inv0 = 1.0f / l0, inv1 = 1.0f / l1;
    size_t o0 = (((size_t)(b * SEQ + qrow0) * NH + h) << 6);
    size_t o1 = (((size_t)(b * SEQ + qrow1) * NH + h) << 6);
#pragma unroll
    for (int nt = 0; nt < 8; nt++) {
        int dim = nt * 8 + (lane & 3) * 2;
        uint32_t hp, lp;
        split_pair(oacc[nt][0] * inv0, oacc[nt][1] * inv0, hp, lp);
        *(uint32_t*)(g_oh + o0 + dim) = hp;
        *(uint32_t*)(g_ol + o0 + dim) = lp;
        split_pair(oacc[nt][2] * inv1, oacc[nt][3] * inv1, hp, lp);
        *(uint32_t*)(g_oh + o1 + dim) = hp;
        *(uint32_t*)(g_ol + o1 + dim) = lp;
    }
}

// ---------------- launch ---------------------------------------------------
extern "C" void kernel_launch(void* const* d_in, const int* in_sizes, int n_in,
                              void* d_out, int out_size)
{
    const float* x    = (const float*)d_in[0];
    const float* cosp = (const float*)d_in[1];
    const float* sinp = (const float*)d_in[2];
    const float* Wq   = (const float*)d_in[3];
    const float* Wk   = (const float*)d_in[4];
    const float* Wv   = (const float*)d_in[5];
    const float* Wo   = (const float*)d_in[6];
    float* out = (float*)d_out;

    float* v;
    __half *xh, *xl, *wqth, *wqtl, *wkvh, *wkvl, *woth, *wotl, *oh, *ol;
    cudaGetSymbolAddress((void**)&v, g_v);
    cudaGetSymbolAddress((void**)&xh, g_xh);
    cudaGetSymbolAddress((void**)&xl, g_xl);
    cudaGetSymbolAddress((void**)&wqth, g_wqth);
    cudaGetSymbolAddress((void**)&wqtl, g_wqtl);
    cudaGetSymbolAddress((void**)&wkvh, g_wkvh);
    cudaGetSymbolAddress((void**)&wkvl, g_wkvl);
    cudaGetSymbolAddress((void**)&woth, g_woth);
    cudaGetSymbolAddress((void**)&wotl, g_wotl);
    cudaGetSymbolAddress((void**)&oh, g_oh);
    cudaGetSymbolAddress((void**)&ol, g_ol);

    cudaFuncSetAttribute(gemm_qkv_kernel,
                         cudaFuncAttributeMaxDynamicSharedMemorySize, GEMM_SMEM);
    cudaFuncSetAttribute(gemm_mma_kernel,
                         cudaFuncAttributeMaxDynamicSharedMemorySize, GEMM_SMEM);
    cudaFuncSetAttribute(attn_mma_kernel,
                         cudaFuncAttributeMaxDynamicSharedMemorySize, ATTN_SMEM);

    dim3 tb(32, 8);
    split_kernel<<<(TOK * D_MODEL / 4 + 255) / 256, 256>>>(x, xh, xl, TOK * D_MODEL / 4);
    wsplit_t_kernel<<<dim3(D_MODEL / 32, D_MODEL / 32), tb>>>(Wq, wqth, wqtl, D_MODEL, D_MODEL, 0);
    wsplit_t_kernel<<<dim3(KVD / 32, D_MODEL / 32), tb>>>(Wk, wkvh, wkvl, D_MODEL, KVD, 0);
    wsplit_t_kernel<<<dim3(KVD / 32, D_MODEL / 32), tb>>>(Wv, wkvh, wkvl, D_MODEL, KVD, KVD);
    wsplit_t_kernel<<<dim3(D_MODEL / 32, D_MODEL / 32), tb>>>(Wo, woth, wotl, D_MODEL, D_MODEL, 0);

    // merged Q|K|V projection: one launch, 24 x 32 CTAs
    gemm_qkv_kernel<<<dim3(24, TOK / GBM), 256, GEMM_SMEM>>>(
        xh, xl, wqth, wqtl, wkvh, wkvl, cosp, sinp, v, D_MODEL);

    vsplit_t_kernel<<<dim3(HD / 32, SEQ / 32, BATCH * NKV), tb>>>();

    attn_mma_kernel<<<dim3(SEQ / 128, NH, BATCH), 256, ATTN_SMEM>>>();

    gemm_mma_kernel<<<dim3(D_MODEL / GBN, TOK / GBM), 256, GEMM_SMEM>>>(
        oh, ol, woth, wotl, out, TOK, D_MODEL, D_MODEL);
}